// round 3
// baseline (speedup 1.0000x reference)
#include <cuda_runtime.h>
#include <math.h>
#include <stdint.h>

// Problem constants
constexpr int S_LEN = 4096;
constexpr int BATCH = 2;
constexpr int EMB   = 512;   // E and also H*D
constexpr int NH    = 8;
constexpr int DH    = 64;
constexpr int HALF  = 256;   // sliding window half-width
constexpr int ROWS  = BATCH * S_LEN;  // 8192

// Scratch (allocation-free rule: __device__ globals)
__device__ float g_q[(size_t)ROWS * EMB];
__device__ float g_k[(size_t)ROWS * EMB];
__device__ float g_v[(size_t)ROWS * EMB];
__device__ float g_att[(size_t)ROWS * EMB];

// ---------------------------------------------------------------------------
// tf32 helpers
// ---------------------------------------------------------------------------
__device__ __forceinline__ uint32_t f2tf32(float x) {
    uint32_t r;
    asm("cvt.rna.tf32.f32 %0, %1;" : "=r"(r) : "f"(x));
    return r;
}

__device__ __forceinline__ void split_tf32(float x, uint32_t& hi, uint32_t& lo) {
    hi = f2tf32(x);
    lo = f2tf32(x - __uint_as_float(hi));
}

__device__ __forceinline__ void mma_tf32(float d[4], const uint32_t a[4],
                                         const uint32_t b[2]) {
    asm volatile(
        "mma.sync.aligned.m16n8k8.row.col.f32.tf32.tf32.f32 "
        "{%0,%1,%2,%3}, {%4,%5,%6,%7}, {%8,%9}, {%0,%1,%2,%3};\n"
        : "+f"(d[0]), "+f"(d[1]), "+f"(d[2]), "+f"(d[3])
        : "r"(a[0]), "r"(a[1]), "r"(a[2]), "r"(a[3]), "r"(b[0]), "r"(b[1]));
}

// ---------------------------------------------------------------------------
// Split-tf32 tensor-core GEMM: C[M,N] = A[M,K] @ B[K,N], row-major.
// CTA tile 128x128, BK=16, 256 threads (8 warps, 2x4 -> 64x32 warp tiles).
// A smem [m][k] stride 20 (frag loads conflict-free: bank=(4m+k)%32 bijective).
// B smem [k][n] stride 132 (frag loads conflict-free: bank=(4k+n)%32 bijective).
// Double-buffered smem stages + register prefetch.
// ---------------------------------------------------------------------------
constexpr int GBM = 128, GBN = 128, GBK = 16;
constexpr int ASTR = 20;    // A smem row stride (words)
constexpr int BSTR = 132;   // B smem row stride (words)
constexpr int A_STAGE = GBM * ASTR;   // 2560 words
constexpr int B_STAGE = GBK * BSTR;   // 2112 words
constexpr int GEMM_SMEM_BYTES = (4 * A_STAGE + 4 * B_STAGE) * 4;  // 74752

__global__ __launch_bounds__(256, 1) void gemm_tf32_kernel(
    const float* __restrict__ A, const float* __restrict__ B,
    float* __restrict__ C, int M, int N, int K)
{
    extern __shared__ uint32_t sm[];
    uint32_t* sAh = sm;                       // [2][A_STAGE]
    uint32_t* sAl = sAh + 2 * A_STAGE;
    uint32_t* sBh = sAl + 2 * A_STAGE;        // [2][B_STAGE]
    uint32_t* sBl = sBh + 2 * B_STAGE;

    const int tid  = threadIdx.x;
    const int lane = tid & 31;
    const int wid  = tid >> 5;
    const int warp_m = wid >> 2;          // 0..1
    const int warp_n = wid & 3;           // 0..3
    const int m_base = warp_m * 64;
    const int n_base = warp_n * 32;
    const int row0 = blockIdx.y * GBM;
    const int col0 = blockIdx.x * GBN;

    // global load mapping
    const int arow = tid >> 2;            // 0..63  (rows arow, arow+64)
    const int acol = (tid & 3) << 2;      // 0,4,8,12
    const int brow = tid >> 5;            // 0..7   (rows brow, brow+8)
    const int bcol = (tid & 31) << 2;     // 0..124

    const float* pA0 = A + (size_t)(row0 + arow) * K + acol;
    const float* pA1 = A + (size_t)(row0 + arow + 64) * K + acol;
    const float* pB0 = B + (size_t)brow * N + col0 + bcol;
    const float* pB1 = B + (size_t)(brow + 8) * N + col0 + bcol;

    const int NT = K / GBK;   // 32 for K=512

    float acc[4][4][4] = {};

    float4 fa0, fa1, fb0, fb1;

    // preload tile 0
    fa0 = *(const float4*)(pA0);
    fa1 = *(const float4*)(pA1);
    fb0 = *(const float4*)(pB0);
    fb1 = *(const float4*)(pB1);

    // store tile 0 to stage 0
    {
        uint32_t h0, l0, h1, l1, h2, l2, h3, l3;
        split_tf32(fa0.x, h0, l0); split_tf32(fa0.y, h1, l1);
        split_tf32(fa0.z, h2, l2); split_tf32(fa0.w, h3, l3);
        *(uint4*)&sAh[arow * ASTR + acol] = make_uint4(h0, h1, h2, h3);
        *(uint4*)&sAl[arow * ASTR + acol] = make_uint4(l0, l1, l2, l3);
        split_tf32(fa1.x, h0, l0); split_tf32(fa1.y, h1, l1);
        split_tf32(fa1.z, h2, l2); split_tf32(fa1.w, h3, l3);
        *(uint4*)&sAh[(arow + 64) * ASTR + acol] = make_uint4(h0, h1, h2, h3);
        *(uint4*)&sAl[(arow + 64) * ASTR + acol] = make_uint4(l0, l1, l2, l3);
        split_tf32(fb0.x, h0, l0); split_tf32(fb0.y, h1, l1);
        split_tf32(fb0.z, h2, l2); split_tf32(fb0.w, h3, l3);
        *(uint4*)&sBh[brow * BSTR + bcol] = make_uint4(h0, h1, h2, h3);
        *(uint4*)&sBl[brow * BSTR + bcol] = make_uint4(l0, l1, l2, l3);
        split_tf32(fb1.x, h0, l0); split_tf32(fb1.y, h1, l1);
        split_tf32(fb1.z, h2, l2); split_tf32(fb1.w, h3, l3);
        *(uint4*)&sBh[(brow + 8) * BSTR + bcol] = make_uint4(h0, h1, h2, h3);
        *(uint4*)&sBl[(brow + 8) * BSTR + bcol] = make_uint4(l0, l1, l2, l3);
    }
    __syncthreads();

    const int qr = lane >> 2;   // 0..7
    const int qc = lane & 3;    // 0..3

    for (int kt = 0; kt < NT; kt++) {
        // prefetch next tile into registers
        if (kt + 1 < NT) {
            int ko = (kt + 1) * GBK;
            fa0 = *(const float4*)(pA0 + ko);
            fa1 = *(const float4*)(pA1 + ko);
            fb0 = *(const float4*)(pB0 + (size_t)ko * N);
            fb1 = *(const float4*)(pB1 + (size_t)ko * N);
        }

        const uint32_t* Ah = sAh + (kt & 1) * A_STAGE;
        const uint32_t* Al = sAl + (kt & 1) * A_STAGE;
        const uint32_t* Bh = sBh + (kt & 1) * B_STAGE;
        const uint32_t* Bl = sBl + (kt & 1) * B_STAGE;

        #pragma unroll
        for (int ks = 0; ks < 2; ks++) {
            const int k0 = ks * 8;
            uint32_t ah[4][4], al[4][4], bh[4][2], bl[4][2];
            #pragma unroll
            for (int mt = 0; mt < 4; mt++) {
                const uint32_t* ph = &Ah[(m_base + mt * 16 + qr) * ASTR + k0 + qc];
                const uint32_t* pl = &Al[(m_base + mt * 16 + qr) * ASTR + k0 + qc];
                ah[mt][0] = ph[0]; ah[mt][1] = ph[8 * ASTR];
                ah[mt][2] = ph[4]; ah[mt][3] = ph[8 * ASTR + 4];
                al[mt][0] = pl[0]; al[mt][1] = pl[8 * ASTR];
                al[mt][2] = pl[4]; al[mt][3] = pl[8 * ASTR + 4];
            }
            #pragma unroll
            for (int nt = 0; nt < 4; nt++) {
                const uint32_t* ph = &Bh[(k0 + qc) * BSTR + n_base + nt * 8 + qr];
                const uint32_t* pl = &Bl[(k0 + qc) * BSTR + n_base + nt * 8 + qr];
                bh[nt][0] = ph[0]; bh[nt][1] = ph[4 * BSTR];
                bl[nt][0] = pl[0]; bl[nt][1] = pl[4 * BSTR];
            }
            #pragma unroll
            for (int mt = 0; mt < 4; mt++)
                #pragma unroll
                for (int nt = 0; nt < 4; nt++) {
                    mma_tf32(acc[mt][nt], ah[mt], bh[nt]);
                    mma_tf32(acc[mt][nt], ah[mt], bl[nt]);
                    mma_tf32(acc[mt][nt], al[mt], bh[nt]);
                }
        }

        // store prefetched tile to the other stage
        if (kt + 1 < NT) {
            uint32_t* dAh = sAh + ((kt + 1) & 1) * A_STAGE;
            uint32_t* dAl = sAl + ((kt + 1) & 1) * A_STAGE;
            uint32_t* dBh = sBh + ((kt + 1) & 1) * B_STAGE;
            uint32_t* dBl = sBl + ((kt + 1) & 1) * B_STAGE;
            uint32_t h0, l0, h1, l1, h2, l2, h3, l3;
            split_tf32(fa0.x, h0, l0); split_tf32(fa0.y, h1, l1);
            split_tf32(fa0.z, h2, l2); split_tf32(fa0.w, h3, l3);
            *(uint4*)&dAh[arow * ASTR + acol] = make_uint4(h0, h1, h2, h3);
            *(uint4*)&dAl[arow * ASTR + acol] = make_uint4(l0, l1, l2, l3);
            split_tf32(fa1.x, h0, l0); split_tf32(fa1.y, h1, l1);
            split_tf32(fa1.z, h2, l2); split_tf32(fa1.w, h3, l3);
            *(uint4*)&dAh[(arow + 64) * ASTR + acol] = make_uint4(h0, h1, h2, h3);
            *(uint4*)&dAl[(arow + 64) * ASTR + acol] = make_uint4(l0, l1, l2, l3);
            split_tf32(fb0.x, h0, l0); split_tf32(fb0.y, h1, l1);
            split_tf32(fb0.z, h2, l2); split_tf32(fb0.w, h3, l3);
            *(uint4*)&dBh[brow * BSTR + bcol] = make_uint4(h0, h1, h2, h3);
            *(uint4*)&dBl[brow * BSTR + bcol] = make_uint4(l0, l1, l2, l3);
            split_tf32(fb1.x, h0, l0); split_tf32(fb1.y, h1, l1);
            split_tf32(fb1.z, h2, l2); split_tf32(fb1.w, h3, l3);
            *(uint4*)&dBh[(brow + 8) * BSTR + bcol] = make_uint4(h0, h1, h2, h3);
            *(uint4*)&dBl[(brow + 8) * BSTR + bcol] = make_uint4(l0, l1, l2, l3);
        }
        __syncthreads();
    }

    // Epilogue: c frag (m16n8): rows qr, qr+8; cols 2*qc, 2*qc+1
    #pragma unroll
    for (int mt = 0; mt < 4; mt++) {
        #pragma unroll
        for (int nt = 0; nt < 4; nt++) {
            int r = row0 + m_base + mt * 16 + qr;
            int c = col0 + n_base + nt * 8 + 2 * qc;
            *(float2*)&C[(size_t)r * N + c] =
                make_float2(acc[mt][nt][0], acc[mt][nt][1]);
            *(float2*)&C[(size_t)(r + 8) * N + c] =
                make_float2(acc[mt][nt][2], acc[mt][nt][3]);
        }
    }
}

// ---------------------------------------------------------------------------
// Windowed flash attention with bidirectional ALiBi (unchanged from R1).
// ---------------------------------------------------------------------------
constexpr int QT = 64;
constexpr int KT = 128;
constexpr int SQ_STRIDE = 68;
constexpr int SK_STRIDE = 132;
constexpr int SMEM_FLOATS = 64*68 + 64*132 + 128*68 + 128*68 + 64*17 + 3*64;
constexpr int SMEM_BYTES  = SMEM_FLOATS * 4;  // 125952

__global__ __launch_bounds__(256) void attn_kernel()
{
    extern __shared__ float smem[];
    float* sQt = smem;                       // 64*68
    float* sKt = sQt + 64 * 68;              // 64*132
    float* sV  = sKt + 64 * 132;             // 128*68
    float* sP  = sV  + 128 * 68;             // 128*68
    float* red = sP  + 128 * 68;             // 64*17
    float* mS  = red + 64 * 17;
    float* lS  = mS + 64;
    float* fS  = lS + 64;

    const int tid = threadIdx.x;
    const int tx = tid & 15;
    const int ty = tid >> 4;
    const int t0 = blockIdx.x * QT;
    const int h  = blockIdx.y;
    const int b  = blockIdx.z;
    const float slope = exp2f(-(float)(h + 1));   // ALiBi slope for H=8

    const float* Qb = g_q   + (size_t)b * S_LEN * EMB + h * DH;
    const float* Kb = g_k   + (size_t)b * S_LEN * EMB + h * DH;
    const float* Vb = g_v   + (size_t)b * S_LEN * EMB + h * DH;
    float*       Ob = g_att + (size_t)b * S_LEN * EMB + h * DH;

    for (int idx = tid; idx < QT * 16; idx += 256) {
        int q = idx >> 4;
        int d = (idx & 15) * 4;
        float4 v = *(const float4*)&Qb[(size_t)(t0 + q) * EMB + d];
        sQt[(d + 0) * SQ_STRIDE + q] = v.x;
        sQt[(d + 1) * SQ_STRIDE + q] = v.y;
        sQt[(d + 2) * SQ_STRIDE + q] = v.z;
        sQt[(d + 3) * SQ_STRIDE + q] = v.w;
    }
    if (tid < QT) { mS[tid] = -1e30f; lS[tid] = 0.0f; }

    float o[4][4] = {};

    const int kbeg = max(0, t0 - HALF);
    const int kend = min(S_LEN, t0 + QT + HALF);

    for (int kstart = kbeg; kstart < kend; kstart += KT) {
        for (int idx = tid; idx < KT * 16; idx += 256) {
            int kk = idx >> 4;
            int d = (idx & 15) * 4;
            int T = kstart + kk;
            float4 kv = make_float4(0.f, 0.f, 0.f, 0.f);
            float4 vv = make_float4(0.f, 0.f, 0.f, 0.f);
            if (T < S_LEN) {
                kv = *(const float4*)&Kb[(size_t)T * EMB + d];
                vv = *(const float4*)&Vb[(size_t)T * EMB + d];
            }
            sKt[(d + 0) * SK_STRIDE + kk] = kv.x;
            sKt[(d + 1) * SK_STRIDE + kk] = kv.y;
            sKt[(d + 2) * SK_STRIDE + kk] = kv.z;
            sKt[(d + 3) * SK_STRIDE + kk] = kv.w;
            *(float4*)&sV[kk * SQ_STRIDE + d] = vv;
        }
        __syncthreads();

        float s[4][8] = {};
        #pragma unroll 8
        for (int d = 0; d < DH; d++) {
            float ra[4], rb[8];
            *(float4*)&ra[0] = *(float4*)&sQt[d * SQ_STRIDE + ty * 4];
            *(float4*)&rb[0] = *(float4*)&sKt[d * SK_STRIDE + tx * 8];
            *(float4*)&rb[4] = *(float4*)&sKt[d * SK_STRIDE + tx * 8 + 4];
            #pragma unroll
            for (int i = 0; i < 4; i++)
                #pragma unroll
                for (int j = 0; j < 8; j++)
                    s[i][j] = fmaf(ra[i], rb[j], s[i][j]);
        }

        #pragma unroll
        for (int i = 0; i < 4; i++) {
            int t = t0 + ty * 4 + i;
            float lmax = -1e30f;
            #pragma unroll
            for (int j = 0; j < 8; j++) {
                int T = kstart + tx * 8 + j;
                int dlt = t - T;
                bool valid = (T < S_LEN) && (dlt <= HALF) && (dlt >= -HALF);
                float val = valid ? fmaf(s[i][j], 0.125f, -slope * fabsf((float)dlt))
                                  : -1e30f;
                s[i][j] = val;
                lmax = fmaxf(lmax, val);
            }
            red[(ty * 4 + i) * 17 + tx] = lmax;
        }
        __syncthreads();

        if (tid < QT) {
            float cm = -1e30f;
            #pragma unroll
            for (int j = 0; j < 16; j++) cm = fmaxf(cm, red[tid * 17 + j]);
            float mold = mS[tid];
            float mnew = fmaxf(mold, cm);
            fS[tid] = __expf(mold - mnew);
            mS[tid] = mnew;
        }
        __syncthreads();

        #pragma unroll
        for (int i = 0; i < 4; i++) {
            int r = ty * 4 + i;
            float mrow = mS[r];
            float sum = 0.f;
            #pragma unroll
            for (int j = 0; j < 8; j++) {
                float p = (s[i][j] > -5e29f) ? __expf(s[i][j] - mrow) : 0.f;
                sP[(tx * 8 + j) * SQ_STRIDE + r] = p;
                sum += p;
            }
            red[r * 17 + tx] = sum;
            float f = fS[r];
            #pragma unroll
            for (int j = 0; j < 4; j++) o[i][j] *= f;
        }
        __syncthreads();

        if (tid < QT) {
            float sum = 0.f;
            #pragma unroll
            for (int j = 0; j < 16; j++) sum += red[tid * 17 + j];
            lS[tid] = lS[tid] * fS[tid] + sum;
        }

        #pragma unroll 8
        for (int kk = 0; kk < KT; kk++) {
            float rp[4], rv[4];
            *(float4*)&rp[0] = *(float4*)&sP[kk * SQ_STRIDE + ty * 4];
            *(float4*)&rv[0] = *(float4*)&sV[kk * SQ_STRIDE + tx * 4];
            #pragma unroll
            for (int i = 0; i < 4; i++)
                #pragma unroll
                for (int j = 0; j < 4; j++)
                    o[i][j] = fmaf(rp[i], rv[j], o[i][j]);
        }
        __syncthreads();
    }

    #pragma unroll
    for (int i = 0; i < 4; i++) {
        int q = ty * 4 + i;
        float li = lS[q];
        float inv = (li > 0.f) ? (1.0f / li) : 0.f;
        float4 v = make_float4(o[i][0] * inv, o[i][1] * inv,
                               o[i][2] * inv, o[i][3] * inv);
        *(float4*)&Ob[(size_t)(t0 + q) * EMB + tx * 4] = v;
    }
}

// ---------------------------------------------------------------------------
extern "C" void kernel_launch(void* const* d_in, const int* in_sizes, int n_in,
                              void* d_out, int out_size)
{
    (void)in_sizes; (void)n_in; (void)out_size;
    const float* inputs_q  = (const float*)d_in[0];
    const float* inputs_kv = (const float*)d_in[1];
    const float* w_q = (const float*)d_in[2];
    const float* w_k = (const float*)d_in[3];
    const float* w_v = (const float*)d_in[4];
    const float* w_o = (const float*)d_in[5];
    float* out = (float*)d_out;

    float *qb, *kb, *vb, *ab;
    cudaGetSymbolAddress((void**)&qb, g_q);
    cudaGetSymbolAddress((void**)&kb, g_k);
    cudaGetSymbolAddress((void**)&vb, g_v);
    cudaGetSymbolAddress((void**)&ab, g_att);

    cudaFuncSetAttribute(attn_kernel,
                         cudaFuncAttributeMaxDynamicSharedMemorySize,
                         SMEM_BYTES);
    cudaFuncSetAttribute(gemm_tf32_kernel,
                         cudaFuncAttributeMaxDynamicSharedMemorySize,
                         GEMM_SMEM_BYTES);

    dim3 gGemm(EMB / GBN, ROWS / GBM);   // (4, 64)
    gemm_tf32_kernel<<<gGemm, 256, GEMM_SMEM_BYTES>>>(inputs_q,  w_q, qb, ROWS, EMB, EMB);
    gemm_tf32_kernel<<<gGemm, 256, GEMM_SMEM_BYTES>>>(inputs_kv, w_k, kb, ROWS, EMB, EMB);
    gemm_tf32_kernel<<<gGemm, 256, GEMM_SMEM_BYTES>>>(inputs_kv, w_v, vb, ROWS, EMB, EMB);

    dim3 gAttn(S_LEN / QT, NH, BATCH);   // (64, 8, 2)
    attn_kernel<<<gAttn, 256, SMEM_BYTES>>>();

    gemm_tf32_kernel<<<gGemm, 256, GEMM_SMEM_BYTES>>>(ab, w_o, out, ROWS, EMB, EMB);
}

// round 4
// speedup vs baseline: 1.4752x; 1.4752x over previous
#include <cuda_runtime.h>
#include <math.h>
#include <stdint.h>

// Problem constants
constexpr int S_LEN = 4096;
constexpr int BATCH = 2;
constexpr int EMB   = 512;   // E and also H*D
constexpr int NH    = 8;
constexpr int DH    = 64;
constexpr int HALF  = 256;   // sliding window half-width
constexpr int ROWS  = BATCH * S_LEN;  // 8192

// Scratch (allocation-free rule: __device__ globals)
__device__ float g_q[(size_t)ROWS * EMB];
__device__ float g_k[(size_t)ROWS * EMB];
__device__ float g_v[(size_t)ROWS * EMB];
__device__ float g_att[(size_t)ROWS * EMB];

// ---------------------------------------------------------------------------
// bf16 split helpers
// ---------------------------------------------------------------------------
// Pack two floats into bf16x2 {lo=x0, hi=x1}, plus residual pack for hi/lo split.
__device__ __forceinline__ void split2(float x0, float x1,
                                       uint32_t& hp, uint32_t& lp) {
    asm("cvt.rn.bf16x2.f32 %0, %1, %2;" : "=r"(hp) : "f"(x1), "f"(x0));
    float h0 = __uint_as_float(hp << 16);
    float h1 = __uint_as_float(hp & 0xffff0000u);
    float r0 = x0 - h0;
    float r1 = x1 - h1;
    asm("cvt.rn.bf16x2.f32 %0, %1, %2;" : "=r"(lp) : "f"(r1), "f"(r0));
}

__device__ __forceinline__ void mma_bf16(float d[4], const uint32_t a[4],
                                         const uint32_t b[2]) {
    asm volatile(
        "mma.sync.aligned.m16n8k16.row.col.f32.bf16.bf16.f32 "
        "{%0,%1,%2,%3}, {%4,%5,%6,%7}, {%8,%9}, {%0,%1,%2,%3};\n"
        : "+f"(d[0]), "+f"(d[1]), "+f"(d[2]), "+f"(d[3])
        : "r"(a[0]), "r"(a[1]), "r"(a[2]), "r"(a[3]), "r"(b[0]), "r"(b[1]));
}

// ---------------------------------------------------------------------------
// tf32 helpers (projection GEMMs, unchanged from R2)
// ---------------------------------------------------------------------------
__device__ __forceinline__ uint32_t f2tf32(float x) {
    uint32_t r;
    asm("cvt.rna.tf32.f32 %0, %1;" : "=r"(r) : "f"(x));
    return r;
}

__device__ __forceinline__ void split_tf32(float x, uint32_t& hi, uint32_t& lo) {
    hi = f2tf32(x);
    lo = f2tf32(x - __uint_as_float(hi));
}

__device__ __forceinline__ void mma_tf32(float d[4], const uint32_t a[4],
                                         const uint32_t b[2]) {
    asm volatile(
        "mma.sync.aligned.m16n8k8.row.col.f32.tf32.tf32.f32 "
        "{%0,%1,%2,%3}, {%4,%5,%6,%7}, {%8,%9}, {%0,%1,%2,%3};\n"
        : "+f"(d[0]), "+f"(d[1]), "+f"(d[2]), "+f"(d[3])
        : "r"(a[0]), "r"(a[1]), "r"(a[2]), "r"(a[3]), "r"(b[0]), "r"(b[1]));
}

// ---------------------------------------------------------------------------
// Split-tf32 tensor-core GEMM (validated in R2). C[M,N] = A[M,K] @ B[K,N].
// ---------------------------------------------------------------------------
constexpr int GBM = 128, GBN = 128, GBK = 16;
constexpr int ASTR = 20;
constexpr int BSTR = 132;
constexpr int A_STAGE = GBM * ASTR;
constexpr int B_STAGE = GBK * BSTR;
constexpr int GEMM_SMEM_BYTES = (4 * A_STAGE + 4 * B_STAGE) * 4;

__global__ __launch_bounds__(256, 1) void gemm_tf32_kernel(
    const float* __restrict__ A, const float* __restrict__ B,
    float* __restrict__ C, int M, int N, int K)
{
    extern __shared__ uint32_t sm[];
    uint32_t* sAh = sm;
    uint32_t* sAl = sAh + 2 * A_STAGE;
    uint32_t* sBh = sAl + 2 * A_STAGE;
    uint32_t* sBl = sBh + 2 * B_STAGE;

    const int tid  = threadIdx.x;
    const int lane = tid & 31;
    const int wid  = tid >> 5;
    const int m_base = (wid >> 2) * 64;
    const int n_base = (wid & 3) * 32;
    const int row0 = blockIdx.y * GBM;
    const int col0 = blockIdx.x * GBN;

    const int arow = tid >> 2;
    const int acol = (tid & 3) << 2;
    const int brow = tid >> 5;
    const int bcol = (tid & 31) << 2;

    const float* pA0 = A + (size_t)(row0 + arow) * K + acol;
    const float* pA1 = A + (size_t)(row0 + arow + 64) * K + acol;
    const float* pB0 = B + (size_t)brow * N + col0 + bcol;
    const float* pB1 = B + (size_t)(brow + 8) * N + col0 + bcol;

    const int NT = K / GBK;

    float acc[4][4][4] = {};
    float4 fa0, fa1, fb0, fb1;

    fa0 = *(const float4*)(pA0);
    fa1 = *(const float4*)(pA1);
    fb0 = *(const float4*)(pB0);
    fb1 = *(const float4*)(pB1);

    {
        uint32_t h0, l0, h1, l1, h2, l2, h3, l3;
        split_tf32(fa0.x, h0, l0); split_tf32(fa0.y, h1, l1);
        split_tf32(fa0.z, h2, l2); split_tf32(fa0.w, h3, l3);
        *(uint4*)&sAh[arow * ASTR + acol] = make_uint4(h0, h1, h2, h3);
        *(uint4*)&sAl[arow * ASTR + acol] = make_uint4(l0, l1, l2, l3);
        split_tf32(fa1.x, h0, l0); split_tf32(fa1.y, h1, l1);
        split_tf32(fa1.z, h2, l2); split_tf32(fa1.w, h3, l3);
        *(uint4*)&sAh[(arow + 64) * ASTR + acol] = make_uint4(h0, h1, h2, h3);
        *(uint4*)&sAl[(arow + 64) * ASTR + acol] = make_uint4(l0, l1, l2, l3);
        split_tf32(fb0.x, h0, l0); split_tf32(fb0.y, h1, l1);
        split_tf32(fb0.z, h2, l2); split_tf32(fb0.w, h3, l3);
        *(uint4*)&sBh[brow * BSTR + bcol] = make_uint4(h0, h1, h2, h3);
        *(uint4*)&sBl[brow * BSTR + bcol] = make_uint4(l0, l1, l2, l3);
        split_tf32(fb1.x, h0, l0); split_tf32(fb1.y, h1, l1);
        split_tf32(fb1.z, h2, l2); split_tf32(fb1.w, h3, l3);
        *(uint4*)&sBh[(brow + 8) * BSTR + bcol] = make_uint4(h0, h1, h2, h3);
        *(uint4*)&sBl[(brow + 8) * BSTR + bcol] = make_uint4(l0, l1, l2, l3);
    }
    __syncthreads();

    const int qr = lane >> 2;
    const int qc = lane & 3;

    for (int kt = 0; kt < NT; kt++) {
        if (kt + 1 < NT) {
            int ko = (kt + 1) * GBK;
            fa0 = *(const float4*)(pA0 + ko);
            fa1 = *(const float4*)(pA1 + ko);
            fb0 = *(const float4*)(pB0 + (size_t)ko * N);
            fb1 = *(const float4*)(pB1 + (size_t)ko * N);
        }

        const uint32_t* Ah = sAh + (kt & 1) * A_STAGE;
        const uint32_t* Al = sAl + (kt & 1) * A_STAGE;
        const uint32_t* Bh = sBh + (kt & 1) * B_STAGE;
        const uint32_t* Bl = sBl + (kt & 1) * B_STAGE;

        #pragma unroll
        for (int ks = 0; ks < 2; ks++) {
            const int k0 = ks * 8;
            uint32_t ah[4][4], al[4][4], bh[4][2], bl[4][2];
            #pragma unroll
            for (int mt = 0; mt < 4; mt++) {
                const uint32_t* ph = &Ah[(m_base + mt * 16 + qr) * ASTR + k0 + qc];
                const uint32_t* pl = &Al[(m_base + mt * 16 + qr) * ASTR + k0 + qc];
                ah[mt][0] = ph[0]; ah[mt][1] = ph[8 * ASTR];
                ah[mt][2] = ph[4]; ah[mt][3] = ph[8 * ASTR + 4];
                al[mt][0] = pl[0]; al[mt][1] = pl[8 * ASTR];
                al[mt][2] = pl[4]; al[mt][3] = pl[8 * ASTR + 4];
            }
            #pragma unroll
            for (int nt = 0; nt < 4; nt++) {
                const uint32_t* ph = &Bh[(k0 + qc) * BSTR + n_base + nt * 8 + qr];
                const uint32_t* pl = &Bl[(k0 + qc) * BSTR + n_base + nt * 8 + qr];
                bh[nt][0] = ph[0]; bh[nt][1] = ph[4 * BSTR];
                bl[nt][0] = pl[0]; bl[nt][1] = pl[4 * BSTR];
            }
            #pragma unroll
            for (int mt = 0; mt < 4; mt++)
                #pragma unroll
                for (int nt = 0; nt < 4; nt++) {
                    mma_tf32(acc[mt][nt], ah[mt], bh[nt]);
                    mma_tf32(acc[mt][nt], ah[mt], bl[nt]);
                    mma_tf32(acc[mt][nt], al[mt], bh[nt]);
                }
        }

        if (kt + 1 < NT) {
            uint32_t* dAh = sAh + ((kt + 1) & 1) * A_STAGE;
            uint32_t* dAl = sAl + ((kt + 1) & 1) * A_STAGE;
            uint32_t* dBh = sBh + ((kt + 1) & 1) * B_STAGE;
            uint32_t* dBl = sBl + ((kt + 1) & 1) * B_STAGE;
            uint32_t h0, l0, h1, l1, h2, l2, h3, l3;
            split_tf32(fa0.x, h0, l0); split_tf32(fa0.y, h1, l1);
            split_tf32(fa0.z, h2, l2); split_tf32(fa0.w, h3, l3);
            *(uint4*)&dAh[arow * ASTR + acol] = make_uint4(h0, h1, h2, h3);
            *(uint4*)&dAl[arow * ASTR + acol] = make_uint4(l0, l1, l2, l3);
            split_tf32(fa1.x, h0, l0); split_tf32(fa1.y, h1, l1);
            split_tf32(fa1.z, h2, l2); split_tf32(fa1.w, h3, l3);
            *(uint4*)&dAh[(arow + 64) * ASTR + acol] = make_uint4(h0, h1, h2, h3);
            *(uint4*)&dAl[(arow + 64) * ASTR + acol] = make_uint4(l0, l1, l2, l3);
            split_tf32(fb0.x, h0, l0); split_tf32(fb0.y, h1, l1);
            split_tf32(fb0.z, h2, l2); split_tf32(fb0.w, h3, l3);
            *(uint4*)&dBh[brow * BSTR + bcol] = make_uint4(h0, h1, h2, h3);
            *(uint4*)&dBl[brow * BSTR + bcol] = make_uint4(l0, l1, l2, l3);
            split_tf32(fb1.x, h0, l0); split_tf32(fb1.y, h1, l1);
            split_tf32(fb1.z, h2, l2); split_tf32(fb1.w, h3, l3);
            *(uint4*)&dBh[(brow + 8) * BSTR + bcol] = make_uint4(h0, h1, h2, h3);
            *(uint4*)&dBl[(brow + 8) * BSTR + bcol] = make_uint4(l0, l1, l2, l3);
        }
        __syncthreads();
    }

    #pragma unroll
    for (int mt = 0; mt < 4; mt++) {
        #pragma unroll
        for (int nt = 0; nt < 4; nt++) {
            int r = row0 + m_base + mt * 16 + qr;
            int c = col0 + n_base + nt * 8 + 2 * qc;
            *(float2*)&C[(size_t)r * N + c] =
                make_float2(acc[mt][nt][0], acc[mt][nt][1]);
            *(float2*)&C[(size_t)(r + 8) * N + c] =
                make_float2(acc[mt][nt][2], acc[mt][nt][3]);
        }
    }
}

// ---------------------------------------------------------------------------
// Tensor-core windowed flash attention, bf16 hi/lo split (3-MMA) everywhere.
// CTA = (b, h, 64-query tile); keys in 3 chunks of 192 (window span = 576).
// 8 warps: QK as 4(m) x 2(n) -> warp tile 16 x 96; PV 4(m) x 2(n) -> 16 x 32.
// All operands packed bf16x2 in smem, kp-major, strides == 8 (mod 32):
// fragment loads are bank-conflict-free.
// ---------------------------------------------------------------------------
constexpr int AQT = 64;    // queries per CTA
constexpr int AKT = 192;   // keys per chunk
constexpr int QSTR = 72;   // sQ stride (u32), 64 q + pad
constexpr int KSTR = 200;  // sK stride, 192 keys + pad
constexpr int VSTR = 72;   // sVt stride, 64 d + pad
constexpr int PSTR = 72;   // sP stride, 64 q + pad

constexpr int OFF_QH = 0;
constexpr int OFF_QL = OFF_QH + 32 * QSTR;     // 2304
constexpr int OFF_KH = OFF_QL + 32 * QSTR;     // 4608
constexpr int OFF_KL = OFF_KH + 32 * KSTR;     // 11008
constexpr int OFF_VH = OFF_KL + 32 * KSTR;     // 17408
constexpr int OFF_VL = OFF_VH + 96 * VSTR;     // 24320
constexpr int OFF_PH = OFF_VL + 96 * VSTR;     // 31232
constexpr int OFF_PL = OFF_PH + 96 * PSTR;     // 38144
constexpr int OFF_RED = OFF_PL + 96 * PSTR;    // 45056 (float[128])
constexpr int OFF_M  = OFF_RED + 128;          // float[64]
constexpr int OFF_L  = OFF_M + 64;
constexpr int OFF_F  = OFF_L + 64;
constexpr int ATTN_SMEM_WORDS = OFF_F + 64;    // 45376
constexpr int ATTN_SMEM_BYTES = ATTN_SMEM_WORDS * 4;  // 181504

__global__ __launch_bounds__(256, 1) void attn_tc_kernel()
{
    extern __shared__ uint32_t sm[];
    uint32_t* sQh = sm + OFF_QH;
    uint32_t* sQl = sm + OFF_QL;
    uint32_t* sKh = sm + OFF_KH;
    uint32_t* sKl = sm + OFF_KL;
    uint32_t* sVh = sm + OFF_VH;
    uint32_t* sVl = sm + OFF_VL;
    uint32_t* sPh = sm + OFF_PH;
    uint32_t* sPl = sm + OFF_PL;
    float* red = (float*)(sm + OFF_RED);
    float* mS  = (float*)(sm + OFF_M);
    float* lS  = (float*)(sm + OFF_L);
    float* fS  = (float*)(sm + OFF_F);

    const int tid  = threadIdx.x;
    const int lane = tid & 31;
    const int wid  = tid >> 5;
    const int gr = lane >> 2;     // group row 0..7
    const int qc = lane & 3;      // quad col 0..3
    const int wm = wid >> 1;      // 0..3
    const int wn = wid & 1;       // 0..1
    const int m0 = wm * 16;

    const int t0 = blockIdx.x * AQT;
    const int h  = blockIdx.y;
    const int b  = blockIdx.z;
    const float slope = exp2f(-(float)(h + 1));

    const float* Qb = g_q   + (size_t)b * S_LEN * EMB + h * DH;
    const float* Kb = g_k   + (size_t)b * S_LEN * EMB + h * DH;
    const float* Vb = g_v   + (size_t)b * S_LEN * EMB + h * DH;
    float*       Ob = g_att + (size_t)b * S_LEN * EMB + h * DH;

    // Load Q tile (split bf16, kp-major)
    for (int idx = tid; idx < AQT * 16; idx += 256) {
        int q = idx >> 4;
        int dg = idx & 15;
        float4 v = *(const float4*)&Qb[(size_t)(t0 + q) * EMB + dg * 4];
        uint32_t h0, l0, h1, l1;
        split2(v.x, v.y, h0, l0);
        split2(v.z, v.w, h1, l1);
        int kp = dg * 2;
        sQh[kp * QSTR + q] = h0;        sQl[kp * QSTR + q] = l0;
        sQh[(kp + 1) * QSTR + q] = h1;  sQl[(kp + 1) * QSTR + q] = l1;
    }
    if (tid < AQT) { mS[tid] = -1e30f; lS[tid] = 0.0f; }

    float o[4][4] = {};

    const int base = t0 - HALF;

    #pragma unroll 1
    for (int c = 0; c < 3; c++) {
        const int cs = base + c * AKT;
        if (cs + AKT <= 0 || cs >= S_LEN) continue;

        // ---- load K chunk (pack along d) ----
        for (int idx = tid; idx < AKT * 16; idx += 256) {
            int key = idx >> 4;
            int dg = idx & 15;
            int T = cs + key;
            float4 kv = make_float4(0.f, 0.f, 0.f, 0.f);
            if (T >= 0 && T < S_LEN)
                kv = *(const float4*)&Kb[(size_t)T * EMB + dg * 4];
            uint32_t h0, l0, h1, l1;
            split2(kv.x, kv.y, h0, l0);
            split2(kv.z, kv.w, h1, l1);
            int kp = dg * 2;
            sKh[kp * KSTR + key] = h0;        sKl[kp * KSTR + key] = l0;
            sKh[(kp + 1) * KSTR + key] = h1;  sKl[(kp + 1) * KSTR + key] = l1;
        }
        // ---- load V chunk transposed (pack along keys) ----
        for (int idx = tid; idx < 96 * 16; idx += 256) {
            int kp = idx >> 4;     // keypair 0..95
            int dg = idx & 15;
            int d = dg * 4;
            int T0 = cs + 2 * kp, T1 = T0 + 1;
            float4 v0 = make_float4(0.f, 0.f, 0.f, 0.f);
            float4 v1 = make_float4(0.f, 0.f, 0.f, 0.f);
            if (T0 >= 0 && T0 < S_LEN) v0 = *(const float4*)&Vb[(size_t)T0 * EMB + d];
            if (T1 >= 0 && T1 < S_LEN) v1 = *(const float4*)&Vb[(size_t)T1 * EMB + d];
            uint32_t hp, lp;
            split2(v0.x, v1.x, hp, lp); sVh[kp * VSTR + d + 0] = hp; sVl[kp * VSTR + d + 0] = lp;
            split2(v0.y, v1.y, hp, lp); sVh[kp * VSTR + d + 1] = hp; sVl[kp * VSTR + d + 1] = lp;
            split2(v0.z, v1.z, hp, lp); sVh[kp * VSTR + d + 2] = hp; sVl[kp * VSTR + d + 2] = lp;
            split2(v0.w, v1.w, hp, lp); sVh[kp * VSTR + d + 3] = hp; sVl[kp * VSTR + d + 3] = lp;
        }
        __syncthreads();

        // ---- S = Q @ K^T : warp tile 16 x 96, 12 n-tiles, 4 k-steps ----
        float s[12][4];
        #pragma unroll
        for (int nt = 0; nt < 12; nt++)
            #pragma unroll
            for (int i = 0; i < 4; i++) s[nt][i] = 0.f;

        const int nbase = wn * 96;
        #pragma unroll
        for (int ks = 0; ks < 4; ks++) {
            const int kpa = ks * 8 + qc;
            uint32_t ah[4], al[4];
            ah[0] = sQh[kpa * QSTR + m0 + gr];
            ah[1] = sQh[kpa * QSTR + m0 + gr + 8];
            ah[2] = sQh[(kpa + 4) * QSTR + m0 + gr];
            ah[3] = sQh[(kpa + 4) * QSTR + m0 + gr + 8];
            al[0] = sQl[kpa * QSTR + m0 + gr];
            al[1] = sQl[kpa * QSTR + m0 + gr + 8];
            al[2] = sQl[(kpa + 4) * QSTR + m0 + gr];
            al[3] = sQl[(kpa + 4) * QSTR + m0 + gr + 8];
            #pragma unroll
            for (int nt = 0; nt < 12; nt++) {
                int n = nbase + nt * 8 + gr;
                uint32_t bh[2], bl[2];
                bh[0] = sKh[kpa * KSTR + n];
                bh[1] = sKh[(kpa + 4) * KSTR + n];
                bl[0] = sKl[kpa * KSTR + n];
                bl[1] = sKl[(kpa + 4) * KSTR + n];
                mma_bf16(s[nt], ah, bh);
                mma_bf16(s[nt], ah, bl);
                mma_bf16(s[nt], al, bh);
            }
        }

        // ---- scale + ALiBi + window mask; per-row max ----
        const int trow0 = t0 + m0 + gr;
        const int trow1 = trow0 + 8;
        float mx0 = -1e30f, mx1 = -1e30f;
        #pragma unroll
        for (int nt = 0; nt < 12; nt++) {
            int T0 = cs + nbase + nt * 8 + 2 * qc;
            int T1 = T0 + 1;
            bool in0 = (T0 >= 0) && (T0 < S_LEN);
            bool in1 = (T1 >= 0) && (T1 < S_LEN);
            int d00 = trow0 - T0, d01 = trow0 - T1;
            int d10 = trow1 - T0, d11 = trow1 - T1;
            int a00 = abs(d00), a01 = abs(d01), a10 = abs(d10), a11 = abs(d11);
            s[nt][0] = (in0 && a00 <= HALF) ? fmaf(s[nt][0], 0.125f, -slope * (float)a00) : -1e30f;
            s[nt][1] = (in1 && a01 <= HALF) ? fmaf(s[nt][1], 0.125f, -slope * (float)a01) : -1e30f;
            s[nt][2] = (in0 && a10 <= HALF) ? fmaf(s[nt][2], 0.125f, -slope * (float)a10) : -1e30f;
            s[nt][3] = (in1 && a11 <= HALF) ? fmaf(s[nt][3], 0.125f, -slope * (float)a11) : -1e30f;
            mx0 = fmaxf(mx0, fmaxf(s[nt][0], s[nt][1]));
            mx1 = fmaxf(mx1, fmaxf(s[nt][2], s[nt][3]));
        }
        mx0 = fmaxf(mx0, __shfl_xor_sync(0xffffffffu, mx0, 1));
        mx0 = fmaxf(mx0, __shfl_xor_sync(0xffffffffu, mx0, 2));
        mx1 = fmaxf(mx1, __shfl_xor_sync(0xffffffffu, mx1, 1));
        mx1 = fmaxf(mx1, __shfl_xor_sync(0xffffffffu, mx1, 2));
        if (qc == 0) {
            red[(m0 + gr) * 2 + wn] = mx0;
            red[(m0 + gr + 8) * 2 + wn] = mx1;
        }
        __syncthreads();

        if (tid < AQT) {
            float cm = fmaxf(red[tid * 2], red[tid * 2 + 1]);
            float mold = mS[tid];
            float mnew = fmaxf(mold, cm);
            fS[tid] = __expf(mold - mnew);
            mS[tid] = mnew;
        }
        __syncthreads();

        // ---- exp, stage P (split bf16), partial sums, rescale O ----
        const float mrow0 = mS[m0 + gr];
        const float mrow1 = mS[m0 + gr + 8];
        float sum0 = 0.f, sum1 = 0.f;
        #pragma unroll
        for (int nt = 0; nt < 12; nt++) {
            float p00 = (s[nt][0] > -5e29f) ? __expf(s[nt][0] - mrow0) : 0.f;
            float p01 = (s[nt][1] > -5e29f) ? __expf(s[nt][1] - mrow0) : 0.f;
            float p10 = (s[nt][2] > -5e29f) ? __expf(s[nt][2] - mrow1) : 0.f;
            float p11 = (s[nt][3] > -5e29f) ? __expf(s[nt][3] - mrow1) : 0.f;
            sum0 += p00 + p01;
            sum1 += p10 + p11;
            int kp = wn * 48 + nt * 4 + qc;
            uint32_t hp, lp;
            split2(p00, p01, hp, lp);
            sPh[kp * PSTR + m0 + gr] = hp;
            sPl[kp * PSTR + m0 + gr] = lp;
            split2(p10, p11, hp, lp);
            sPh[kp * PSTR + m0 + gr + 8] = hp;
            sPl[kp * PSTR + m0 + gr + 8] = lp;
        }
        sum0 += __shfl_xor_sync(0xffffffffu, sum0, 1);
        sum0 += __shfl_xor_sync(0xffffffffu, sum0, 2);
        sum1 += __shfl_xor_sync(0xffffffffu, sum1, 1);
        sum1 += __shfl_xor_sync(0xffffffffu, sum1, 2);
        if (qc == 0) {
            red[(m0 + gr) * 2 + wn] = sum0;
            red[(m0 + gr + 8) * 2 + wn] = sum1;
        }
        const float f0 = fS[m0 + gr];
        const float f1 = fS[m0 + gr + 8];
        #pragma unroll
        for (int nt = 0; nt < 4; nt++) {
            o[nt][0] *= f0; o[nt][1] *= f0;
            o[nt][2] *= f1; o[nt][3] *= f1;
        }
        __syncthreads();

        if (tid < AQT)
            lS[tid] = lS[tid] * fS[tid] + red[tid * 2] + red[tid * 2 + 1];

        // ---- O += P @ V : warp tile 16 x 32, 4 n-tiles, 12 k-steps ----
        const int nb2 = wn * 32;
        #pragma unroll
        for (int ks = 0; ks < 12; ks++) {
            const int kpa = ks * 8 + qc;
            uint32_t ah[4], al[4];
            ah[0] = sPh[kpa * PSTR + m0 + gr];
            ah[1] = sPh[kpa * PSTR + m0 + gr + 8];
            ah[2] = sPh[(kpa + 4) * PSTR + m0 + gr];
            ah[3] = sPh[(kpa + 4) * PSTR + m0 + gr + 8];
            al[0] = sPl[kpa * PSTR + m0 + gr];
            al[1] = sPl[kpa * PSTR + m0 + gr + 8];
            al[2] = sPl[(kpa + 4) * PSTR + m0 + gr];
            al[3] = sPl[(kpa + 4) * PSTR + m0 + gr + 8];
            #pragma unroll
            for (int nt = 0; nt < 4; nt++) {
                int n = nb2 + nt * 8 + gr;
                uint32_t bh[2], bl[2];
                bh[0] = sVh[kpa * VSTR + n];
                bh[1] = sVh[(kpa + 4) * VSTR + n];
                bl[0] = sVl[kpa * VSTR + n];
                bl[1] = sVl[(kpa + 4) * VSTR + n];
                mma_bf16(o[nt], ah, bh);
                mma_bf16(o[nt], ah, bl);
                mma_bf16(o[nt], al, bh);
            }
        }
        __syncthreads();
    }

    // ---- normalize and write ----
    const int trow0 = t0 + m0 + gr;
    const float inv0 = 1.0f / lS[m0 + gr];
    const float inv1 = 1.0f / lS[m0 + gr + 8];
    #pragma unroll
    for (int nt = 0; nt < 4; nt++) {
        int d = wn * 32 + nt * 8 + 2 * qc;
        *(float2*)&Ob[(size_t)trow0 * EMB + d] =
            make_float2(o[nt][0] * inv0, o[nt][1] * inv0);
        *(float2*)&Ob[(size_t)(trow0 + 8) * EMB + d] =
            make_float2(o[nt][2] * inv1, o[nt][3] * inv1);
    }
}

// ---------------------------------------------------------------------------
extern "C" void kernel_launch(void* const* d_in, const int* in_sizes, int n_in,
                              void* d_out, int out_size)
{
    (void)in_sizes; (void)n_in; (void)out_size;
    const float* inputs_q  = (const float*)d_in[0];
    const float* inputs_kv = (const float*)d_in[1];
    const float* w_q = (const float*)d_in[2];
    const float* w_k = (const float*)d_in[3];
    const float* w_v = (const float*)d_in[4];
    const float* w_o = (const float*)d_in[5];
    float* out = (float*)d_out;

    float *qb, *kb, *vb, *ab;
    cudaGetSymbolAddress((void**)&qb, g_q);
    cudaGetSymbolAddress((void**)&kb, g_k);
    cudaGetSymbolAddress((void**)&vb, g_v);
    cudaGetSymbolAddress((void**)&ab, g_att);

    cudaFuncSetAttribute(gemm_tf32_kernel,
                         cudaFuncAttributeMaxDynamicSharedMemorySize,
                         GEMM_SMEM_BYTES);
    cudaFuncSetAttribute(attn_tc_kernel,
                         cudaFuncAttributeMaxDynamicSharedMemorySize,
                         ATTN_SMEM_BYTES);

    dim3 gGemm(EMB / GBN, ROWS / GBM);   // (4, 64)
    gemm_tf32_kernel<<<gGemm, 256, GEMM_SMEM_BYTES>>>(inputs_q,  w_q, qb, ROWS, EMB, EMB);
    gemm_tf32_kernel<<<gGemm, 256, GEMM_SMEM_BYTES>>>(inputs_kv, w_k, kb, ROWS, EMB, EMB);
    gemm_tf32_kernel<<<gGemm, 256, GEMM_SMEM_BYTES>>>(inputs_kv, w_v, vb, ROWS, EMB, EMB);

    dim3 gAttn(S_LEN / AQT, NH, BATCH);  // (64, 8, 2)
    attn_tc_kernel<<<gAttn, 256, ATTN_SMEM_BYTES>>>();

    gemm_tf32_kernel<<<gGemm, 256, GEMM_SMEM_BYTES>>>(ab, w_o, out, ROWS, EMB, EMB);
}

// round 5
// speedup vs baseline: 1.4760x; 1.0005x over previous
#include <cuda_runtime.h>
#include <math.h>
#include <stdint.h>

// Problem constants
constexpr int S_LEN = 4096;
constexpr int BATCH = 2;
constexpr int EMB   = 512;   // E and also H*D
constexpr int NH    = 8;
constexpr int DH    = 64;
constexpr int HALF  = 256;   // sliding window half-width
constexpr int ROWS  = BATCH * S_LEN;  // 8192

// Scratch (allocation-free rule: __device__ globals)
__device__ float g_q[(size_t)ROWS * EMB];
__device__ float g_k[(size_t)ROWS * EMB];
__device__ float g_v[(size_t)ROWS * EMB];
__device__ float g_att[(size_t)ROWS * EMB];

// ---------------------------------------------------------------------------
// bf16 split helpers
// ---------------------------------------------------------------------------
// Pack two floats into bf16x2 {lo=x0, hi=x1}, plus residual pack for hi/lo split.
__device__ __forceinline__ void split2(float x0, float x1,
                                       uint32_t& hp, uint32_t& lp) {
    asm("cvt.rn.bf16x2.f32 %0, %1, %2;" : "=r"(hp) : "f"(x1), "f"(x0));
    float h0 = __uint_as_float(hp << 16);
    float h1 = __uint_as_float(hp & 0xffff0000u);
    float r0 = x0 - h0;
    float r1 = x1 - h1;
    asm("cvt.rn.bf16x2.f32 %0, %1, %2;" : "=r"(lp) : "f"(r1), "f"(r0));
}

__device__ __forceinline__ void mma_bf16(float d[4], const uint32_t a[4],
                                         const uint32_t b[2]) {
    asm volatile(
        "mma.sync.aligned.m16n8k16.row.col.f32.bf16.bf16.f32 "
        "{%0,%1,%2,%3}, {%4,%5,%6,%7}, {%8,%9}, {%0,%1,%2,%3};\n"
        : "+f"(d[0]), "+f"(d[1]), "+f"(d[2]), "+f"(d[3])
        : "r"(a[0]), "r"(a[1]), "r"(a[2]), "r"(a[3]), "r"(b[0]), "r"(b[1]));
}

// ---------------------------------------------------------------------------
// tf32 helpers (projection GEMMs, unchanged from R2)
// ---------------------------------------------------------------------------
__device__ __forceinline__ uint32_t f2tf32(float x) {
    uint32_t r;
    asm("cvt.rna.tf32.f32 %0, %1;" : "=r"(r) : "f"(x));
    return r;
}

__device__ __forceinline__ void split_tf32(float x, uint32_t& hi, uint32_t& lo) {
    hi = f2tf32(x);
    lo = f2tf32(x - __uint_as_float(hi));
}

__device__ __forceinline__ void mma_tf32(float d[4], const uint32_t a[4],
                                         const uint32_t b[2]) {
    asm volatile(
        "mma.sync.aligned.m16n8k8.row.col.f32.tf32.tf32.f32 "
        "{%0,%1,%2,%3}, {%4,%5,%6,%7}, {%8,%9}, {%0,%1,%2,%3};\n"
        : "+f"(d[0]), "+f"(d[1]), "+f"(d[2]), "+f"(d[3])
        : "r"(a[0]), "r"(a[1]), "r"(a[2]), "r"(a[3]), "r"(b[0]), "r"(b[1]));
}

// ---------------------------------------------------------------------------
// Split-tf32 tensor-core GEMM (validated in R2). C[M,N] = A[M,K] @ B[K,N].
// ---------------------------------------------------------------------------
constexpr int GBM = 128, GBN = 128, GBK = 16;
constexpr int ASTR = 20;
constexpr int BSTR = 132;
constexpr int A_STAGE = GBM * ASTR;
constexpr int B_STAGE = GBK * BSTR;
constexpr int GEMM_SMEM_BYTES = (4 * A_STAGE + 4 * B_STAGE) * 4;

__global__ __launch_bounds__(256, 1) void gemm_tf32_kernel(
    const float* __restrict__ A, const float* __restrict__ B,
    float* __restrict__ C, int M, int N, int K)
{
    extern __shared__ uint32_t sm[];
    uint32_t* sAh = sm;
    uint32_t* sAl = sAh + 2 * A_STAGE;
    uint32_t* sBh = sAl + 2 * A_STAGE;
    uint32_t* sBl = sBh + 2 * B_STAGE;

    const int tid  = threadIdx.x;
    const int lane = tid & 31;
    const int wid  = tid >> 5;
    const int m_base = (wid >> 2) * 64;
    const int n_base = (wid & 3) * 32;
    const int row0 = blockIdx.y * GBM;
    const int col0 = blockIdx.x * GBN;

    const int arow = tid >> 2;
    const int acol = (tid & 3) << 2;
    const int brow = tid >> 5;
    const int bcol = (tid & 31) << 2;

    const float* pA0 = A + (size_t)(row0 + arow) * K + acol;
    const float* pA1 = A + (size_t)(row0 + arow + 64) * K + acol;
    const float* pB0 = B + (size_t)brow * N + col0 + bcol;
    const float* pB1 = B + (size_t)(brow + 8) * N + col0 + bcol;

    const int NT = K / GBK;

    float acc[4][4][4] = {};
    float4 fa0, fa1, fb0, fb1;

    fa0 = *(const float4*)(pA0);
    fa1 = *(const float4*)(pA1);
    fb0 = *(const float4*)(pB0);
    fb1 = *(const float4*)(pB1);

    {
        uint32_t h0, l0, h1, l1, h2, l2, h3, l3;
        split_tf32(fa0.x, h0, l0); split_tf32(fa0.y, h1, l1);
        split_tf32(fa0.z, h2, l2); split_tf32(fa0.w, h3, l3);
        *(uint4*)&sAh[arow * ASTR + acol] = make_uint4(h0, h1, h2, h3);
        *(uint4*)&sAl[arow * ASTR + acol] = make_uint4(l0, l1, l2, l3);
        split_tf32(fa1.x, h0, l0); split_tf32(fa1.y, h1, l1);
        split_tf32(fa1.z, h2, l2); split_tf32(fa1.w, h3, l3);
        *(uint4*)&sAh[(arow + 64) * ASTR + acol] = make_uint4(h0, h1, h2, h3);
        *(uint4*)&sAl[(arow + 64) * ASTR + acol] = make_uint4(l0, l1, l2, l3);
        split_tf32(fb0.x, h0, l0); split_tf32(fb0.y, h1, l1);
        split_tf32(fb0.z, h2, l2); split_tf32(fb0.w, h3, l3);
        *(uint4*)&sBh[brow * BSTR + bcol] = make_uint4(h0, h1, h2, h3);
        *(uint4*)&sBl[brow * BSTR + bcol] = make_uint4(l0, l1, l2, l3);
        split_tf32(fb1.x, h0, l0); split_tf32(fb1.y, h1, l1);
        split_tf32(fb1.z, h2, l2); split_tf32(fb1.w, h3, l3);
        *(uint4*)&sBh[(brow + 8) * BSTR + bcol] = make_uint4(h0, h1, h2, h3);
        *(uint4*)&sBl[(brow + 8) * BSTR + bcol] = make_uint4(l0, l1, l2, l3);
    }
    __syncthreads();

    const int qr = lane >> 2;
    const int qc = lane & 3;

    for (int kt = 0; kt < NT; kt++) {
        if (kt + 1 < NT) {
            int ko = (kt + 1) * GBK;
            fa0 = *(const float4*)(pA0 + ko);
            fa1 = *(const float4*)(pA1 + ko);
            fb0 = *(const float4*)(pB0 + (size_t)ko * N);
            fb1 = *(const float4*)(pB1 + (size_t)ko * N);
        }

        const uint32_t* Ah = sAh + (kt & 1) * A_STAGE;
        const uint32_t* Al = sAl + (kt & 1) * A_STAGE;
        const uint32_t* Bh = sBh + (kt & 1) * B_STAGE;
        const uint32_t* Bl = sBl + (kt & 1) * B_STAGE;

        #pragma unroll
        for (int ks = 0; ks < 2; ks++) {
            const int k0 = ks * 8;
            uint32_t ah[4][4], al[4][4], bh[4][2], bl[4][2];
            #pragma unroll
            for (int mt = 0; mt < 4; mt++) {
                const uint32_t* ph = &Ah[(m_base + mt * 16 + qr) * ASTR + k0 + qc];
                const uint32_t* pl = &Al[(m_base + mt * 16 + qr) * ASTR + k0 + qc];
                ah[mt][0] = ph[0]; ah[mt][1] = ph[8 * ASTR];
                ah[mt][2] = ph[4]; ah[mt][3] = ph[8 * ASTR + 4];
                al[mt][0] = pl[0]; al[mt][1] = pl[8 * ASTR];
                al[mt][2] = pl[4]; al[mt][3] = pl[8 * ASTR + 4];
            }
            #pragma unroll
            for (int nt = 0; nt < 4; nt++) {
                const uint32_t* ph = &Bh[(k0 + qc) * BSTR + n_base + nt * 8 + qr];
                const uint32_t* pl = &Bl[(k0 + qc) * BSTR + n_base + nt * 8 + qr];
                bh[nt][0] = ph[0]; bh[nt][1] = ph[4 * BSTR];
                bl[nt][0] = pl[0]; bl[nt][1] = pl[4 * BSTR];
            }
            #pragma unroll
            for (int mt = 0; mt < 4; mt++)
                #pragma unroll
                for (int nt = 0; nt < 4; nt++) {
                    mma_tf32(acc[mt][nt], ah[mt], bh[nt]);
                    mma_tf32(acc[mt][nt], ah[mt], bl[nt]);
                    mma_tf32(acc[mt][nt], al[mt], bh[nt]);
                }
        }

        if (kt + 1 < NT) {
            uint32_t* dAh = sAh + ((kt + 1) & 1) * A_STAGE;
            uint32_t* dAl = sAl + ((kt + 1) & 1) * A_STAGE;
            uint32_t* dBh = sBh + ((kt + 1) & 1) * B_STAGE;
            uint32_t* dBl = sBl + ((kt + 1) & 1) * B_STAGE;
            uint32_t h0, l0, h1, l1, h2, l2, h3, l3;
            split_tf32(fa0.x, h0, l0); split_tf32(fa0.y, h1, l1);
            split_tf32(fa0.z, h2, l2); split_tf32(fa0.w, h3, l3);
            *(uint4*)&dAh[arow * ASTR + acol] = make_uint4(h0, h1, h2, h3);
            *(uint4*)&dAl[arow * ASTR + acol] = make_uint4(l0, l1, l2, l3);
            split_tf32(fa1.x, h0, l0); split_tf32(fa1.y, h1, l1);
            split_tf32(fa1.z, h2, l2); split_tf32(fa1.w, h3, l3);
            *(uint4*)&dAh[(arow + 64) * ASTR + acol] = make_uint4(h0, h1, h2, h3);
            *(uint4*)&dAl[(arow + 64) * ASTR + acol] = make_uint4(l0, l1, l2, l3);
            split_tf32(fb0.x, h0, l0); split_tf32(fb0.y, h1, l1);
            split_tf32(fb0.z, h2, l2); split_tf32(fb0.w, h3, l3);
            *(uint4*)&dBh[brow * BSTR + bcol] = make_uint4(h0, h1, h2, h3);
            *(uint4*)&dBl[brow * BSTR + bcol] = make_uint4(l0, l1, l2, l3);
            split_tf32(fb1.x, h0, l0); split_tf32(fb1.y, h1, l1);
            split_tf32(fb1.z, h2, l2); split_tf32(fb1.w, h3, l3);
            *(uint4*)&dBh[(brow + 8) * BSTR + bcol] = make_uint4(h0, h1, h2, h3);
            *(uint4*)&dBl[(brow + 8) * BSTR + bcol] = make_uint4(l0, l1, l2, l3);
        }
        __syncthreads();
    }

    #pragma unroll
    for (int mt = 0; mt < 4; mt++) {
        #pragma unroll
        for (int nt = 0; nt < 4; nt++) {
            int r = row0 + m_base + mt * 16 + qr;
            int c = col0 + n_base + nt * 8 + 2 * qc;
            *(float2*)&C[(size_t)r * N + c] =
                make_float2(acc[mt][nt][0], acc[mt][nt][1]);
            *(float2*)&C[(size_t)(r + 8) * N + c] =
                make_float2(acc[mt][nt][2], acc[mt][nt][3]);
        }
    }
}

// ---------------------------------------------------------------------------
// Tensor-core windowed flash attention, bf16 hi/lo split (3-MMA) everywhere.
// CTA = (b, h, 64-query tile); keys in 3 chunks of 192 (window span = 576).
// 8 warps: QK as 4(m) x 2(n) -> warp tile 16 x 96; PV 4(m) x 2(n) -> 16 x 32.
// All operands packed bf16x2 in smem, kp-major, strides == 8 (mod 32):
// fragment loads are bank-conflict-free.
// ---------------------------------------------------------------------------
constexpr int AQT = 64;    // queries per CTA
constexpr int AKT = 192;   // keys per chunk
constexpr int QSTR = 72;   // sQ stride (u32), 64 q + pad
constexpr int KSTR = 200;  // sK stride, 192 keys + pad
constexpr int VSTR = 72;   // sVt stride, 64 d + pad
constexpr int PSTR = 72;   // sP stride, 64 q + pad

constexpr int OFF_QH = 0;
constexpr int OFF_QL = OFF_QH + 32 * QSTR;     // 2304
constexpr int OFF_KH = OFF_QL + 32 * QSTR;     // 4608
constexpr int OFF_KL = OFF_KH + 32 * KSTR;     // 11008
constexpr int OFF_VH = OFF_KL + 32 * KSTR;     // 17408
constexpr int OFF_VL = OFF_VH + 96 * VSTR;     // 24320
constexpr int OFF_PH = OFF_VL + 96 * VSTR;     // 31232
constexpr int OFF_PL = OFF_PH + 96 * PSTR;     // 38144
constexpr int OFF_RED = OFF_PL + 96 * PSTR;    // 45056 (float[128])
constexpr int OFF_M  = OFF_RED + 128;          // float[64]
constexpr int OFF_L  = OFF_M + 64;
constexpr int OFF_F  = OFF_L + 64;
constexpr int ATTN_SMEM_WORDS = OFF_F + 64;    // 45376
constexpr int ATTN_SMEM_BYTES = ATTN_SMEM_WORDS * 4;  // 181504

__global__ __launch_bounds__(256, 1) void attn_tc_kernel()
{
    extern __shared__ uint32_t sm[];
    uint32_t* sQh = sm + OFF_QH;
    uint32_t* sQl = sm + OFF_QL;
    uint32_t* sKh = sm + OFF_KH;
    uint32_t* sKl = sm + OFF_KL;
    uint32_t* sVh = sm + OFF_VH;
    uint32_t* sVl = sm + OFF_VL;
    uint32_t* sPh = sm + OFF_PH;
    uint32_t* sPl = sm + OFF_PL;
    float* red = (float*)(sm + OFF_RED);
    float* mS  = (float*)(sm + OFF_M);
    float* lS  = (float*)(sm + OFF_L);
    float* fS  = (float*)(sm + OFF_F);

    const int tid  = threadIdx.x;
    const int lane = tid & 31;
    const int wid  = tid >> 5;
    const int gr = lane >> 2;     // group row 0..7
    const int qc = lane & 3;      // quad col 0..3
    const int wm = wid >> 1;      // 0..3
    const int wn = wid & 1;       // 0..1
    const int m0 = wm * 16;

    const int t0 = blockIdx.x * AQT;
    const int h  = blockIdx.y;
    const int b  = blockIdx.z;
    const float slope = exp2f(-(float)(h + 1));

    const float* Qb = g_q   + (size_t)b * S_LEN * EMB + h * DH;
    const float* Kb = g_k   + (size_t)b * S_LEN * EMB + h * DH;
    const float* Vb = g_v   + (size_t)b * S_LEN * EMB + h * DH;
    float*       Ob = g_att + (size_t)b * S_LEN * EMB + h * DH;

    // Load Q tile (split bf16, kp-major)
    for (int idx = tid; idx < AQT * 16; idx += 256) {
        int q = idx >> 4;
        int dg = idx & 15;
        float4 v = *(const float4*)&Qb[(size_t)(t0 + q) * EMB + dg * 4];
        uint32_t h0, l0, h1, l1;
        split2(v.x, v.y, h0, l0);
        split2(v.z, v.w, h1, l1);
        int kp = dg * 2;
        sQh[kp * QSTR + q] = h0;        sQl[kp * QSTR + q] = l0;
        sQh[(kp + 1) * QSTR + q] = h1;  sQl[(kp + 1) * QSTR + q] = l1;
    }
    if (tid < AQT) { mS[tid] = -1e30f; lS[tid] = 0.0f; }

    float o[4][4] = {};

    const int base = t0 - HALF;

    #pragma unroll 1
    for (int c = 0; c < 3; c++) {
        const int cs = base + c * AKT;
        if (cs + AKT <= 0 || cs >= S_LEN) continue;

        // ---- load K chunk (pack along d) ----
        for (int idx = tid; idx < AKT * 16; idx += 256) {
            int key = idx >> 4;
            int dg = idx & 15;
            int T = cs + key;
            float4 kv = make_float4(0.f, 0.f, 0.f, 0.f);
            if (T >= 0 && T < S_LEN)
                kv = *(const float4*)&Kb[(size_t)T * EMB + dg * 4];
            uint32_t h0, l0, h1, l1;
            split2(kv.x, kv.y, h0, l0);
            split2(kv.z, kv.w, h1, l1);
            int kp = dg * 2;
            sKh[kp * KSTR + key] = h0;        sKl[kp * KSTR + key] = l0;
            sKh[(kp + 1) * KSTR + key] = h1;  sKl[(kp + 1) * KSTR + key] = l1;
        }
        // ---- load V chunk transposed (pack along keys) ----
        for (int idx = tid; idx < 96 * 16; idx += 256) {
            int kp = idx >> 4;     // keypair 0..95
            int dg = idx & 15;
            int d = dg * 4;
            int T0 = cs + 2 * kp, T1 = T0 + 1;
            float4 v0 = make_float4(0.f, 0.f, 0.f, 0.f);
            float4 v1 = make_float4(0.f, 0.f, 0.f, 0.f);
            if (T0 >= 0 && T0 < S_LEN) v0 = *(const float4*)&Vb[(size_t)T0 * EMB + d];
            if (T1 >= 0 && T1 < S_LEN) v1 = *(const float4*)&Vb[(size_t)T1 * EMB + d];
            uint32_t hp, lp;
            split2(v0.x, v1.x, hp, lp); sVh[kp * VSTR + d + 0] = hp; sVl[kp * VSTR + d + 0] = lp;
            split2(v0.y, v1.y, hp, lp); sVh[kp * VSTR + d + 1] = hp; sVl[kp * VSTR + d + 1] = lp;
            split2(v0.z, v1.z, hp, lp); sVh[kp * VSTR + d + 2] = hp; sVl[kp * VSTR + d + 2] = lp;
            split2(v0.w, v1.w, hp, lp); sVh[kp * VSTR + d + 3] = hp; sVl[kp * VSTR + d + 3] = lp;
        }
        __syncthreads();

        // ---- S = Q @ K^T : warp tile 16 x 96, 12 n-tiles, 4 k-steps ----
        float s[12][4];
        #pragma unroll
        for (int nt = 0; nt < 12; nt++)
            #pragma unroll
            for (int i = 0; i < 4; i++) s[nt][i] = 0.f;

        const int nbase = wn * 96;
        #pragma unroll
        for (int ks = 0; ks < 4; ks++) {
            const int kpa = ks * 8 + qc;
            uint32_t ah[4], al[4];
            ah[0] = sQh[kpa * QSTR + m0 + gr];
            ah[1] = sQh[kpa * QSTR + m0 + gr + 8];
            ah[2] = sQh[(kpa + 4) * QSTR + m0 + gr];
            ah[3] = sQh[(kpa + 4) * QSTR + m0 + gr + 8];
            al[0] = sQl[kpa * QSTR + m0 + gr];
            al[1] = sQl[kpa * QSTR + m0 + gr + 8];
            al[2] = sQl[(kpa + 4) * QSTR + m0 + gr];
            al[3] = sQl[(kpa + 4) * QSTR + m0 + gr + 8];
            #pragma unroll
            for (int nt = 0; nt < 12; nt++) {
                int n = nbase + nt * 8 + gr;
                uint32_t bh[2], bl[2];
                bh[0] = sKh[kpa * KSTR + n];
                bh[1] = sKh[(kpa + 4) * KSTR + n];
                bl[0] = sKl[kpa * KSTR + n];
                bl[1] = sKl[(kpa + 4) * KSTR + n];
                mma_bf16(s[nt], ah, bh);
                mma_bf16(s[nt], ah, bl);
                mma_bf16(s[nt], al, bh);
            }
        }

        // ---- scale + ALiBi + window mask; per-row max ----
        const int trow0 = t0 + m0 + gr;
        const int trow1 = trow0 + 8;
        float mx0 = -1e30f, mx1 = -1e30f;
        #pragma unroll
        for (int nt = 0; nt < 12; nt++) {
            int T0 = cs + nbase + nt * 8 + 2 * qc;
            int T1 = T0 + 1;
            bool in0 = (T0 >= 0) && (T0 < S_LEN);
            bool in1 = (T1 >= 0) && (T1 < S_LEN);
            int d00 = trow0 - T0, d01 = trow0 - T1;
            int d10 = trow1 - T0, d11 = trow1 - T1;
            int a00 = abs(d00), a01 = abs(d01), a10 = abs(d10), a11 = abs(d11);
            s[nt][0] = (in0 && a00 <= HALF) ? fmaf(s[nt][0], 0.125f, -slope * (float)a00) : -1e30f;
            s[nt][1] = (in1 && a01 <= HALF) ? fmaf(s[nt][1], 0.125f, -slope * (float)a01) : -1e30f;
            s[nt][2] = (in0 && a10 <= HALF) ? fmaf(s[nt][2], 0.125f, -slope * (float)a10) : -1e30f;
            s[nt][3] = (in1 && a11 <= HALF) ? fmaf(s[nt][3], 0.125f, -slope * (float)a11) : -1e30f;
            mx0 = fmaxf(mx0, fmaxf(s[nt][0], s[nt][1]));
            mx1 = fmaxf(mx1, fmaxf(s[nt][2], s[nt][3]));
        }
        mx0 = fmaxf(mx0, __shfl_xor_sync(0xffffffffu, mx0, 1));
        mx0 = fmaxf(mx0, __shfl_xor_sync(0xffffffffu, mx0, 2));
        mx1 = fmaxf(mx1, __shfl_xor_sync(0xffffffffu, mx1, 1));
        mx1 = fmaxf(mx1, __shfl_xor_sync(0xffffffffu, mx1, 2));
        if (qc == 0) {
            red[(m0 + gr) * 2 + wn] = mx0;
            red[(m0 + gr + 8) * 2 + wn] = mx1;
        }
        __syncthreads();

        if (tid < AQT) {
            float cm = fmaxf(red[tid * 2], red[tid * 2 + 1]);
            float mold = mS[tid];
            float mnew = fmaxf(mold, cm);
            fS[tid] = __expf(mold - mnew);
            mS[tid] = mnew;
        }
        __syncthreads();

        // ---- exp, stage P (split bf16), partial sums, rescale O ----
        const float mrow0 = mS[m0 + gr];
        const float mrow1 = mS[m0 + gr + 8];
        float sum0 = 0.f, sum1 = 0.f;
        #pragma unroll
        for (int nt = 0; nt < 12; nt++) {
            float p00 = (s[nt][0] > -5e29f) ? __expf(s[nt][0] - mrow0) : 0.f;
            float p01 = (s[nt][1] > -5e29f) ? __expf(s[nt][1] - mrow0) : 0.f;
            float p10 = (s[nt][2] > -5e29f) ? __expf(s[nt][2] - mrow1) : 0.f;
            float p11 = (s[nt][3] > -5e29f) ? __expf(s[nt][3] - mrow1) : 0.f;
            sum0 += p00 + p01;
            sum1 += p10 + p11;
            int kp = wn * 48 + nt * 4 + qc;
            uint32_t hp, lp;
            split2(p00, p01, hp, lp);
            sPh[kp * PSTR + m0 + gr] = hp;
            sPl[kp * PSTR + m0 + gr] = lp;
            split2(p10, p11, hp, lp);
            sPh[kp * PSTR + m0 + gr + 8] = hp;
            sPl[kp * PSTR + m0 + gr + 8] = lp;
        }
        sum0 += __shfl_xor_sync(0xffffffffu, sum0, 1);
        sum0 += __shfl_xor_sync(0xffffffffu, sum0, 2);
        sum1 += __shfl_xor_sync(0xffffffffu, sum1, 1);
        sum1 += __shfl_xor_sync(0xffffffffu, sum1, 2);
        if (qc == 0) {
            red[(m0 + gr) * 2 + wn] = sum0;
            red[(m0 + gr + 8) * 2 + wn] = sum1;
        }
        const float f0 = fS[m0 + gr];
        const float f1 = fS[m0 + gr + 8];
        #pragma unroll
        for (int nt = 0; nt < 4; nt++) {
            o[nt][0] *= f0; o[nt][1] *= f0;
            o[nt][2] *= f1; o[nt][3] *= f1;
        }
        __syncthreads();

        if (tid < AQT)
            lS[tid] = lS[tid] * fS[tid] + red[tid * 2] + red[tid * 2 + 1];

        // ---- O += P @ V : warp tile 16 x 32, 4 n-tiles, 12 k-steps ----
        const int nb2 = wn * 32;
        #pragma unroll
        for (int ks = 0; ks < 12; ks++) {
            const int kpa = ks * 8 + qc;
            uint32_t ah[4], al[4];
            ah[0] = sPh[kpa * PSTR + m0 + gr];
            ah[1] = sPh[kpa * PSTR + m0 + gr + 8];
            ah[2] = sPh[(kpa + 4) * PSTR + m0 + gr];
            ah[3] = sPh[(kpa + 4) * PSTR + m0 + gr + 8];
            al[0] = sPl[kpa * PSTR + m0 + gr];
            al[1] = sPl[kpa * PSTR + m0 + gr + 8];
            al[2] = sPl[(kpa + 4) * PSTR + m0 + gr];
            al[3] = sPl[(kpa + 4) * PSTR + m0 + gr + 8];
            #pragma unroll
            for (int nt = 0; nt < 4; nt++) {
                int n = nb2 + nt * 8 + gr;
                uint32_t bh[2], bl[2];
                bh[0] = sVh[kpa * VSTR + n];
                bh[1] = sVh[(kpa + 4) * VSTR + n];
                bl[0] = sVl[kpa * VSTR + n];
                bl[1] = sVl[(kpa + 4) * VSTR + n];
                mma_bf16(o[nt], ah, bh);
                mma_bf16(o[nt], ah, bl);
                mma_bf16(o[nt], al, bh);
            }
        }
        __syncthreads();
    }

    // ---- normalize and write ----
    const int trow0 = t0 + m0 + gr;
    const float inv0 = 1.0f / lS[m0 + gr];
    const float inv1 = 1.0f / lS[m0 + gr + 8];
    #pragma unroll
    for (int nt = 0; nt < 4; nt++) {
        int d = wn * 32 + nt * 8 + 2 * qc;
        *(float2*)&Ob[(size_t)trow0 * EMB + d] =
            make_float2(o[nt][0] * inv0, o[nt][1] * inv0);
        *(float2*)&Ob[(size_t)(trow0 + 8) * EMB + d] =
            make_float2(o[nt][2] * inv1, o[nt][3] * inv1);
    }
}

// ---------------------------------------------------------------------------
extern "C" void kernel_launch(void* const* d_in, const int* in_sizes, int n_in,
                              void* d_out, int out_size)
{
    (void)in_sizes; (void)n_in; (void)out_size;
    const float* inputs_q  = (const float*)d_in[0];
    const float* inputs_kv = (const float*)d_in[1];
    const float* w_q = (const float*)d_in[2];
    const float* w_k = (const float*)d_in[3];
    const float* w_v = (const float*)d_in[4];
    const float* w_o = (const float*)d_in[5];
    float* out = (float*)d_out;

    float *qb, *kb, *vb, *ab;
    cudaGetSymbolAddress((void**)&qb, g_q);
    cudaGetSymbolAddress((void**)&kb, g_k);
    cudaGetSymbolAddress((void**)&vb, g_v);
    cudaGetSymbolAddress((void**)&ab, g_att);

    cudaFuncSetAttribute(gemm_tf32_kernel,
                         cudaFuncAttributeMaxDynamicSharedMemorySize,
                         GEMM_SMEM_BYTES);
    cudaFuncSetAttribute(attn_tc_kernel,
                         cudaFuncAttributeMaxDynamicSharedMemorySize,
                         ATTN_SMEM_BYTES);

    dim3 gGemm(EMB / GBN, ROWS / GBM);   // (4, 64)
    gemm_tf32_kernel<<<gGemm, 256, GEMM_SMEM_BYTES>>>(inputs_q,  w_q, qb, ROWS, EMB, EMB);
    gemm_tf32_kernel<<<gGemm, 256, GEMM_SMEM_BYTES>>>(inputs_kv, w_k, kb, ROWS, EMB, EMB);
    gemm_tf32_kernel<<<gGemm, 256, GEMM_SMEM_BYTES>>>(inputs_kv, w_v, vb, ROWS, EMB, EMB);

    dim3 gAttn(S_LEN / AQT, NH, BATCH);  // (64, 8, 2)
    attn_tc_kernel<<<gAttn, 256, ATTN_SMEM_BYTES>>>();

    gemm_tf32_kernel<<<gGemm, 256, GEMM_SMEM_BYTES>>>(ab, w_o, out, ROWS, EMB, EMB);
}

// round 6
// speedup vs baseline: 2.1023x; 1.4244x over previous
#include <cuda_runtime.h>
#include <math.h>
#include <stdint.h>

// Problem constants
constexpr int S_LEN = 4096;
constexpr int BATCH = 2;
constexpr int EMB   = 512;   // E and also H*D
constexpr int NH    = 8;
constexpr int DH    = 64;
constexpr int HALF  = 256;   // sliding window half-width
constexpr int ROWS  = BATCH * S_LEN;  // 8192

// Scratch (allocation-free rule: __device__ globals)
__device__ float g_q[(size_t)ROWS * EMB];
__device__ float g_k[(size_t)ROWS * EMB];
__device__ float g_v[(size_t)ROWS * EMB];
__device__ float g_att[(size_t)ROWS * EMB];

// ---------------------------------------------------------------------------
// bf16 split helpers
// ---------------------------------------------------------------------------
__device__ __forceinline__ void split2(float x0, float x1,
                                       uint32_t& hp, uint32_t& lp) {
    asm("cvt.rn.bf16x2.f32 %0, %1, %2;" : "=r"(hp) : "f"(x1), "f"(x0));
    float h0 = __uint_as_float(hp << 16);
    float h1 = __uint_as_float(hp & 0xffff0000u);
    float r0 = x0 - h0;
    float r1 = x1 - h1;
    asm("cvt.rn.bf16x2.f32 %0, %1, %2;" : "=r"(lp) : "f"(r1), "f"(r0));
}

__device__ __forceinline__ void mma_bf16(float d[4], const uint32_t a[4],
                                         const uint32_t b[2]) {
    asm volatile(
        "mma.sync.aligned.m16n8k16.row.col.f32.bf16.bf16.f32 "
        "{%0,%1,%2,%3}, {%4,%5,%6,%7}, {%8,%9}, {%0,%1,%2,%3};\n"
        : "+f"(d[0]), "+f"(d[1]), "+f"(d[2]), "+f"(d[3])
        : "r"(a[0]), "r"(a[1]), "r"(a[2]), "r"(a[3]), "r"(b[0]), "r"(b[1]));
}

// ---------------------------------------------------------------------------
// Split-bf16 tensor-core GEMM: C[M,N] = A[M,K] @ B[K,N], row-major.
// CTA tile 128x128, BK=32 (16 kpairs), 256 threads, 8 warps (2x4 -> 64x32).
// A smem [m][kp] stride 20  (frag bank (gr*20+qc)%32 conflict-free; uint4 stores)
// B smem [kp][n] stride 136 (frag bank (qc*8+gr)%32 bijective;     uint4 stores)
// Double-buffered + register prefetch. 3-MMA hi/lo split (drops lo*lo ~2^-18).
// ---------------------------------------------------------------------------
constexpr int GBM = 128, GBN = 128, GBK = 32;
constexpr int KP  = GBK / 2;            // 16 kpairs per tile
constexpr int ASTR = 20;                // A smem row stride (u32 words)
constexpr int BSTR = 136;               // B smem row stride
constexpr int A_STAGE = GBM * ASTR;     // 2560
constexpr int B_STAGE = KP * BSTR;      // 2176
constexpr int GEMM_SMEM_BYTES = (4 * A_STAGE + 4 * B_STAGE) * 4;  // 75776

__global__ __launch_bounds__(256, 1) void gemm_bf16_kernel(
    const float* __restrict__ A, const float* __restrict__ B,
    float* __restrict__ C, int M, int N, int K)
{
    extern __shared__ uint32_t sm[];
    uint32_t* sAh = sm;                       // [2][A_STAGE]
    uint32_t* sAl = sAh + 2 * A_STAGE;
    uint32_t* sBh = sAl + 2 * A_STAGE;        // [2][B_STAGE]
    uint32_t* sBl = sBh + 2 * B_STAGE;

    const int tid  = threadIdx.x;
    const int lane = tid & 31;
    const int wid  = tid >> 5;
    const int m_base = (wid >> 2) * 64;
    const int n_base = (wid & 3) * 32;
    const int row0 = blockIdx.y * GBM;
    const int col0 = blockIdx.x * GBN;

    // A global mapping: rows arow, arow+64; 8 floats at col acolg
    const int arow  = tid >> 2;           // 0..63
    const int acolg = (tid & 3) * 8;      // 0,8,16,24
    const int akp   = (tid & 3) * 4;      // kpair base for stores
    // B global mapping: kpairs brow, brow+8; 4 cols at bcol
    const int brow = tid >> 5;            // 0..7
    const int bcol = (tid & 31) * 4;      // 0..124

    const float* pA0 = A + (size_t)(row0 + arow) * K + acolg;
    const float* pA1 = A + (size_t)(row0 + arow + 64) * K + acolg;
    const float* pB00 = B + (size_t)(2 * brow) * N + col0 + bcol;
    const float* pB01 = B + (size_t)(2 * brow + 1) * N + col0 + bcol;
    const float* pB10 = B + (size_t)(2 * (brow + 8)) * N + col0 + bcol;
    const float* pB11 = B + (size_t)(2 * (brow + 8) + 1) * N + col0 + bcol;

    const int NT = K / GBK;   // 16 for K=512

    float acc[4][4][4] = {};

    float4 fa00, fa01, fa10, fa11;        // A: 2 rows x 8 floats
    float4 fb00, fb01, fb10, fb11;        // B: 2 kpair-rows x (2 k) x 4 cols

    // helper macro: pack+store one A row (8 floats -> 4 kpairs)
    #define STORE_A(dsth, dstl, r, v0, v1)                                    \
        {                                                                     \
            uint32_t h0, l0, h1, l1, h2, l2, h3, l3;                          \
            split2((v0).x, (v0).y, h0, l0);                                   \
            split2((v0).z, (v0).w, h1, l1);                                   \
            split2((v1).x, (v1).y, h2, l2);                                   \
            split2((v1).z, (v1).w, h3, l3);                                   \
            *(uint4*)&(dsth)[(r) * ASTR + akp] = make_uint4(h0, h1, h2, h3);  \
            *(uint4*)&(dstl)[(r) * ASTR + akp] = make_uint4(l0, l1, l2, l3);  \
        }

    // helper macro: pack+store one B kpair row (2x4 floats -> 4 cols)
    #define STORE_B(dsth, dstl, kp, v0, v1)                                   \
        {                                                                     \
            uint32_t h0, l0, h1, l1, h2, l2, h3, l3;                          \
            split2((v0).x, (v1).x, h0, l0);                                   \
            split2((v0).y, (v1).y, h1, l1);                                   \
            split2((v0).z, (v1).z, h2, l2);                                   \
            split2((v0).w, (v1).w, h3, l3);                                   \
            *(uint4*)&(dsth)[(kp) * BSTR + bcol] = make_uint4(h0, h1, h2, h3);\
            *(uint4*)&(dstl)[(kp) * BSTR + bcol] = make_uint4(l0, l1, l2, l3);\
        }

    // preload tile 0
    fa00 = *(const float4*)(pA0);
    fa01 = *(const float4*)(pA0 + 4);
    fa10 = *(const float4*)(pA1);
    fa11 = *(const float4*)(pA1 + 4);
    fb00 = *(const float4*)(pB00);
    fb01 = *(const float4*)(pB01);
    fb10 = *(const float4*)(pB10);
    fb11 = *(const float4*)(pB11);

    STORE_A(sAh, sAl, arow, fa00, fa01);
    STORE_A(sAh, sAl, arow + 64, fa10, fa11);
    STORE_B(sBh, sBl, brow, fb00, fb01);
    STORE_B(sBh, sBl, brow + 8, fb10, fb11);
    __syncthreads();

    const int gr = lane >> 2;
    const int qc = lane & 3;

    for (int kt = 0; kt < NT; kt++) {
        if (kt + 1 < NT) {
            int ko = (kt + 1) * GBK;
            fa00 = *(const float4*)(pA0 + ko);
            fa01 = *(const float4*)(pA0 + ko + 4);
            fa10 = *(const float4*)(pA1 + ko);
            fa11 = *(const float4*)(pA1 + ko + 4);
            fb00 = *(const float4*)(pB00 + (size_t)ko * N);
            fb01 = *(const float4*)(pB01 + (size_t)ko * N);
            fb10 = *(const float4*)(pB10 + (size_t)ko * N);
            fb11 = *(const float4*)(pB11 + (size_t)ko * N);
        }

        const uint32_t* Ah = sAh + (kt & 1) * A_STAGE;
        const uint32_t* Al = sAl + (kt & 1) * A_STAGE;
        const uint32_t* Bh = sBh + (kt & 1) * B_STAGE;
        const uint32_t* Bl = sBl + (kt & 1) * B_STAGE;

        #pragma unroll
        for (int ks = 0; ks < 2; ks++) {
            const int kp0 = ks * 8 + qc;
            uint32_t ah[4][4], al[4][4], bh[4][2], bl[4][2];
            #pragma unroll
            for (int mt = 0; mt < 4; mt++) {
                const int m = m_base + mt * 16 + gr;
                ah[mt][0] = Ah[m * ASTR + kp0];
                ah[mt][1] = Ah[(m + 8) * ASTR + kp0];
                ah[mt][2] = Ah[m * ASTR + kp0 + 4];
                ah[mt][3] = Ah[(m + 8) * ASTR + kp0 + 4];
                al[mt][0] = Al[m * ASTR + kp0];
                al[mt][1] = Al[(m + 8) * ASTR + kp0];
                al[mt][2] = Al[m * ASTR + kp0 + 4];
                al[mt][3] = Al[(m + 8) * ASTR + kp0 + 4];
            }
            #pragma unroll
            for (int nt = 0; nt < 4; nt++) {
                const int n = n_base + nt * 8 + gr;
                bh[nt][0] = Bh[kp0 * BSTR + n];
                bh[nt][1] = Bh[(kp0 + 4) * BSTR + n];
                bl[nt][0] = Bl[kp0 * BSTR + n];
                bl[nt][1] = Bl[(kp0 + 4) * BSTR + n];
            }
            #pragma unroll
            for (int mt = 0; mt < 4; mt++)
                #pragma unroll
                for (int nt = 0; nt < 4; nt++) {
                    mma_bf16(acc[mt][nt], ah[mt], bh[nt]);
                    mma_bf16(acc[mt][nt], ah[mt], bl[nt]);
                    mma_bf16(acc[mt][nt], al[mt], bh[nt]);
                }
        }

        if (kt + 1 < NT) {
            uint32_t* dAh = sAh + ((kt + 1) & 1) * A_STAGE;
            uint32_t* dAl = sAl + ((kt + 1) & 1) * A_STAGE;
            uint32_t* dBh = sBh + ((kt + 1) & 1) * B_STAGE;
            uint32_t* dBl = sBl + ((kt + 1) & 1) * B_STAGE;
            STORE_A(dAh, dAl, arow, fa00, fa01);
            STORE_A(dAh, dAl, arow + 64, fa10, fa11);
            STORE_B(dBh, dBl, brow, fb00, fb01);
            STORE_B(dBh, dBl, brow + 8, fb10, fb11);
        }
        __syncthreads();
    }
    #undef STORE_A
    #undef STORE_B

    // Epilogue: rows gr/gr+8, cols 2qc/2qc+1 per m16n8 tile
    #pragma unroll
    for (int mt = 0; mt < 4; mt++) {
        #pragma unroll
        for (int nt = 0; nt < 4; nt++) {
            int r = row0 + m_base + mt * 16 + gr;
            int c = col0 + n_base + nt * 8 + 2 * qc;
            *(float2*)&C[(size_t)r * N + c] =
                make_float2(acc[mt][nt][0], acc[mt][nt][1]);
            *(float2*)&C[(size_t)(r + 8) * N + c] =
                make_float2(acc[mt][nt][2], acc[mt][nt][3]);
        }
    }
}

// ---------------------------------------------------------------------------
// Tensor-core windowed flash attention, bf16 hi/lo split (unchanged from R3).
// ---------------------------------------------------------------------------
constexpr int AQT = 64;
constexpr int AKT = 192;
constexpr int QSTR = 72;
constexpr int KSTR = 200;
constexpr int VSTR = 72;
constexpr int PSTR = 72;

constexpr int OFF_QH = 0;
constexpr int OFF_QL = OFF_QH + 32 * QSTR;
constexpr int OFF_KH = OFF_QL + 32 * QSTR;
constexpr int OFF_KL = OFF_KH + 32 * KSTR;
constexpr int OFF_VH = OFF_KL + 32 * KSTR;
constexpr int OFF_VL = OFF_VH + 96 * VSTR;
constexpr int OFF_PH = OFF_VL + 96 * VSTR;
constexpr int OFF_PL = OFF_PH + 96 * PSTR;
constexpr int OFF_RED = OFF_PL + 96 * PSTR;
constexpr int OFF_M  = OFF_RED + 128;
constexpr int OFF_L  = OFF_M + 64;
constexpr int OFF_F  = OFF_L + 64;
constexpr int ATTN_SMEM_WORDS = OFF_F + 64;
constexpr int ATTN_SMEM_BYTES = ATTN_SMEM_WORDS * 4;  // 181504

__global__ __launch_bounds__(256, 1) void attn_tc_kernel()
{
    extern __shared__ uint32_t sm[];
    uint32_t* sQh = sm + OFF_QH;
    uint32_t* sQl = sm + OFF_QL;
    uint32_t* sKh = sm + OFF_KH;
    uint32_t* sKl = sm + OFF_KL;
    uint32_t* sVh = sm + OFF_VH;
    uint32_t* sVl = sm + OFF_VL;
    uint32_t* sPh = sm + OFF_PH;
    uint32_t* sPl = sm + OFF_PL;
    float* red = (float*)(sm + OFF_RED);
    float* mS  = (float*)(sm + OFF_M);
    float* lS  = (float*)(sm + OFF_L);
    float* fS  = (float*)(sm + OFF_F);

    const int tid  = threadIdx.x;
    const int lane = tid & 31;
    const int wid  = tid >> 5;
    const int gr = lane >> 2;
    const int qc = lane & 3;
    const int wm = wid >> 1;
    const int wn = wid & 1;
    const int m0 = wm * 16;

    const int t0 = blockIdx.x * AQT;
    const int h  = blockIdx.y;
    const int b  = blockIdx.z;
    const float slope = exp2f(-(float)(h + 1));

    const float* Qb = g_q   + (size_t)b * S_LEN * EMB + h * DH;
    const float* Kb = g_k   + (size_t)b * S_LEN * EMB + h * DH;
    const float* Vb = g_v   + (size_t)b * S_LEN * EMB + h * DH;
    float*       Ob = g_att + (size_t)b * S_LEN * EMB + h * DH;

    for (int idx = tid; idx < AQT * 16; idx += 256) {
        int q = idx >> 4;
        int dg = idx & 15;
        float4 v = *(const float4*)&Qb[(size_t)(t0 + q) * EMB + dg * 4];
        uint32_t h0, l0, h1, l1;
        split2(v.x, v.y, h0, l0);
        split2(v.z, v.w, h1, l1);
        int kp = dg * 2;
        sQh[kp * QSTR + q] = h0;        sQl[kp * QSTR + q] = l0;
        sQh[(kp + 1) * QSTR + q] = h1;  sQl[(kp + 1) * QSTR + q] = l1;
    }
    if (tid < AQT) { mS[tid] = -1e30f; lS[tid] = 0.0f; }

    float o[4][4] = {};

    const int base = t0 - HALF;

    #pragma unroll 1
    for (int c = 0; c < 3; c++) {
        const int cs = base + c * AKT;
        if (cs + AKT <= 0 || cs >= S_LEN) continue;

        for (int idx = tid; idx < AKT * 16; idx += 256) {
            int key = idx >> 4;
            int dg = idx & 15;
            int T = cs + key;
            float4 kv = make_float4(0.f, 0.f, 0.f, 0.f);
            if (T >= 0 && T < S_LEN)
                kv = *(const float4*)&Kb[(size_t)T * EMB + dg * 4];
            uint32_t h0, l0, h1, l1;
            split2(kv.x, kv.y, h0, l0);
            split2(kv.z, kv.w, h1, l1);
            int kp = dg * 2;
            sKh[kp * KSTR + key] = h0;        sKl[kp * KSTR + key] = l0;
            sKh[(kp + 1) * KSTR + key] = h1;  sKl[(kp + 1) * KSTR + key] = l1;
        }
        for (int idx = tid; idx < 96 * 16; idx += 256) {
            int kp = idx >> 4;
            int dg = idx & 15;
            int d = dg * 4;
            int T0 = cs + 2 * kp, T1 = T0 + 1;
            float4 v0 = make_float4(0.f, 0.f, 0.f, 0.f);
            float4 v1 = make_float4(0.f, 0.f, 0.f, 0.f);
            if (T0 >= 0 && T0 < S_LEN) v0 = *(const float4*)&Vb[(size_t)T0 * EMB + d];
            if (T1 >= 0 && T1 < S_LEN) v1 = *(const float4*)&Vb[(size_t)T1 * EMB + d];
            uint32_t hp, lp;
            split2(v0.x, v1.x, hp, lp); sVh[kp * VSTR + d + 0] = hp; sVl[kp * VSTR + d + 0] = lp;
            split2(v0.y, v1.y, hp, lp); sVh[kp * VSTR + d + 1] = hp; sVl[kp * VSTR + d + 1] = lp;
            split2(v0.z, v1.z, hp, lp); sVh[kp * VSTR + d + 2] = hp; sVl[kp * VSTR + d + 2] = lp;
            split2(v0.w, v1.w, hp, lp); sVh[kp * VSTR + d + 3] = hp; sVl[kp * VSTR + d + 3] = lp;
        }
        __syncthreads();

        float s[12][4];
        #pragma unroll
        for (int nt = 0; nt < 12; nt++)
            #pragma unroll
            for (int i = 0; i < 4; i++) s[nt][i] = 0.f;

        const int nbase = wn * 96;
        #pragma unroll
        for (int ks = 0; ks < 4; ks++) {
            const int kpa = ks * 8 + qc;
            uint32_t ah[4], al[4];
            ah[0] = sQh[kpa * QSTR + m0 + gr];
            ah[1] = sQh[kpa * QSTR + m0 + gr + 8];
            ah[2] = sQh[(kpa + 4) * QSTR + m0 + gr];
            ah[3] = sQh[(kpa + 4) * QSTR + m0 + gr + 8];
            al[0] = sQl[kpa * QSTR + m0 + gr];
            al[1] = sQl[kpa * QSTR + m0 + gr + 8];
            al[2] = sQl[(kpa + 4) * QSTR + m0 + gr];
            al[3] = sQl[(kpa + 4) * QSTR + m0 + gr + 8];
            #pragma unroll
            for (int nt = 0; nt < 12; nt++) {
                int n = nbase + nt * 8 + gr;
                uint32_t bh[2], bl[2];
                bh[0] = sKh[kpa * KSTR + n];
                bh[1] = sKh[(kpa + 4) * KSTR + n];
                bl[0] = sKl[kpa * KSTR + n];
                bl[1] = sKl[(kpa + 4) * KSTR + n];
                mma_bf16(s[nt], ah, bh);
                mma_bf16(s[nt], ah, bl);
                mma_bf16(s[nt], al, bh);
            }
        }

        const int trow0 = t0 + m0 + gr;
        const int trow1 = trow0 + 8;
        float mx0 = -1e30f, mx1 = -1e30f;
        #pragma unroll
        for (int nt = 0; nt < 12; nt++) {
            int T0 = cs + nbase + nt * 8 + 2 * qc;
            int T1 = T0 + 1;
            bool in0 = (T0 >= 0) && (T0 < S_LEN);
            bool in1 = (T1 >= 0) && (T1 < S_LEN);
            int d00 = trow0 - T0, d01 = trow0 - T1;
            int d10 = trow1 - T0, d11 = trow1 - T1;
            int a00 = abs(d00), a01 = abs(d01), a10 = abs(d10), a11 = abs(d11);
            s[nt][0] = (in0 && a00 <= HALF) ? fmaf(s[nt][0], 0.125f, -slope * (float)a00) : -1e30f;
            s[nt][1] = (in1 && a01 <= HALF) ? fmaf(s[nt][1], 0.125f, -slope * (float)a01) : -1e30f;
            s[nt][2] = (in0 && a10 <= HALF) ? fmaf(s[nt][2], 0.125f, -slope * (float)a10) : -1e30f;
            s[nt][3] = (in1 && a11 <= HALF) ? fmaf(s[nt][3], 0.125f, -slope * (float)a11) : -1e30f;
            mx0 = fmaxf(mx0, fmaxf(s[nt][0], s[nt][1]));
            mx1 = fmaxf(mx1, fmaxf(s[nt][2], s[nt][3]));
        }
        mx0 = fmaxf(mx0, __shfl_xor_sync(0xffffffffu, mx0, 1));
        mx0 = fmaxf(mx0, __shfl_xor_sync(0xffffffffu, mx0, 2));
        mx1 = fmaxf(mx1, __shfl_xor_sync(0xffffffffu, mx1, 1));
        mx1 = fmaxf(mx1, __shfl_xor_sync(0xffffffffu, mx1, 2));
        if (qc == 0) {
            red[(m0 + gr) * 2 + wn] = mx0;
            red[(m0 + gr + 8) * 2 + wn] = mx1;
        }
        __syncthreads();

        if (tid < AQT) {
            float cm = fmaxf(red[tid * 2], red[tid * 2 + 1]);
            float mold = mS[tid];
            float mnew = fmaxf(mold, cm);
            fS[tid] = __expf(mold - mnew);
            mS[tid] = mnew;
        }
        __syncthreads();

        const float mrow0 = mS[m0 + gr];
        const float mrow1 = mS[m0 + gr + 8];
        float sum0 = 0.f, sum1 = 0.f;
        #pragma unroll
        for (int nt = 0; nt < 12; nt++) {
            float p00 = (s[nt][0] > -5e29f) ? __expf(s[nt][0] - mrow0) : 0.f;
            float p01 = (s[nt][1] > -5e29f) ? __expf(s[nt][1] - mrow0) : 0.f;
            float p10 = (s[nt][2] > -5e29f) ? __expf(s[nt][2] - mrow1) : 0.f;
            float p11 = (s[nt][3] > -5e29f) ? __expf(s[nt][3] - mrow1) : 0.f;
            sum0 += p00 + p01;
            sum1 += p10 + p11;
            int kp = wn * 48 + nt * 4 + qc;
            uint32_t hp, lp;
            split2(p00, p01, hp, lp);
            sPh[kp * PSTR + m0 + gr] = hp;
            sPl[kp * PSTR + m0 + gr] = lp;
            split2(p10, p11, hp, lp);
            sPh[kp * PSTR + m0 + gr + 8] = hp;
            sPl[kp * PSTR + m0 + gr + 8] = lp;
        }
        sum0 += __shfl_xor_sync(0xffffffffu, sum0, 1);
        sum0 += __shfl_xor_sync(0xffffffffu, sum0, 2);
        sum1 += __shfl_xor_sync(0xffffffffu, sum1, 1);
        sum1 += __shfl_xor_sync(0xffffffffu, sum1, 2);
        if (qc == 0) {
            red[(m0 + gr) * 2 + wn] = sum0;
            red[(m0 + gr + 8) * 2 + wn] = sum1;
        }
        const float f0 = fS[m0 + gr];
        const float f1 = fS[m0 + gr + 8];
        #pragma unroll
        for (int nt = 0; nt < 4; nt++) {
            o[nt][0] *= f0; o[nt][1] *= f0;
            o[nt][2] *= f1; o[nt][3] *= f1;
        }
        __syncthreads();

        if (tid < AQT)
            lS[tid] = lS[tid] * fS[tid] + red[tid * 2] + red[tid * 2 + 1];

        const int nb2 = wn * 32;
        #pragma unroll
        for (int ks = 0; ks < 12; ks++) {
            const int kpa = ks * 8 + qc;
            uint32_t ah[4], al[4];
            ah[0] = sPh[kpa * PSTR + m0 + gr];
            ah[1] = sPh[kpa * PSTR + m0 + gr + 8];
            ah[2] = sPh[(kpa + 4) * PSTR + m0 + gr];
            ah[3] = sPh[(kpa + 4) * PSTR + m0 + gr + 8];
            al[0] = sPl[kpa * PSTR + m0 + gr];
            al[1] = sPl[kpa * PSTR + m0 + gr + 8];
            al[2] = sPl[(kpa + 4) * PSTR + m0 + gr];
            al[3] = sPl[(kpa + 4) * PSTR + m0 + gr + 8];
            #pragma unroll
            for (int nt = 0; nt < 4; nt++) {
                int n = nb2 + nt * 8 + gr;
                uint32_t bh[2], bl[2];
                bh[0] = sVh[kpa * VSTR + n];
                bh[1] = sVh[(kpa + 4) * VSTR + n];
                bl[0] = sVl[kpa * VSTR + n];
                bl[1] = sVl[(kpa + 4) * VSTR + n];
                mma_bf16(o[nt], ah, bh);
                mma_bf16(o[nt], ah, bl);
                mma_bf16(o[nt], al, bh);
            }
        }
        __syncthreads();
    }

    const int trow0 = t0 + m0 + gr;
    const float inv0 = 1.0f / lS[m0 + gr];
    const float inv1 = 1.0f / lS[m0 + gr + 8];
    #pragma unroll
    for (int nt = 0; nt < 4; nt++) {
        int d = wn * 32 + nt * 8 + 2 * qc;
        *(float2*)&Ob[(size_t)trow0 * EMB + d] =
            make_float2(o[nt][0] * inv0, o[nt][1] * inv0);
        *(float2*)&Ob[(size_t)(trow0 + 8) * EMB + d] =
            make_float2(o[nt][2] * inv1, o[nt][3] * inv1);
    }
}

// ---------------------------------------------------------------------------
extern "C" void kernel_launch(void* const* d_in, const int* in_sizes, int n_in,
                              void* d_out, int out_size)
{
    (void)in_sizes; (void)n_in; (void)out_size;
    const float* inputs_q  = (const float*)d_in[0];
    const float* inputs_kv = (const float*)d_in[1];
    const float* w_q = (const float*)d_in[2];
    const float* w_k = (const float*)d_in[3];
    const float* w_v = (const float*)d_in[4];
    const float* w_o = (const float*)d_in[5];
    float* out = (float*)d_out;

    float *qb, *kb, *vb, *ab;
    cudaGetSymbolAddress((void**)&qb, g_q);
    cudaGetSymbolAddress((void**)&kb, g_k);
    cudaGetSymbolAddress((void**)&vb, g_v);
    cudaGetSymbolAddress((void**)&ab, g_att);

    cudaFuncSetAttribute(gemm_bf16_kernel,
                         cudaFuncAttributeMaxDynamicSharedMemorySize,
                         GEMM_SMEM_BYTES);
    cudaFuncSetAttribute(attn_tc_kernel,
                         cudaFuncAttributeMaxDynamicSharedMemorySize,
                         ATTN_SMEM_BYTES);

    dim3 gGemm(EMB / GBN, ROWS / GBM);   // (4, 64)
    gemm_bf16_kernel<<<gGemm, 256, GEMM_SMEM_BYTES>>>(inputs_q,  w_q, qb, ROWS, EMB, EMB);
    gemm_bf16_kernel<<<gGemm, 256, GEMM_SMEM_BYTES>>>(inputs_kv, w_k, kb, ROWS, EMB, EMB);
    gemm_bf16_kernel<<<gGemm, 256, GEMM_SMEM_BYTES>>>(inputs_kv, w_v, vb, ROWS, EMB, EMB);

    dim3 gAttn(S_LEN / AQT, NH, BATCH);  // (64, 8, 2)
    attn_tc_kernel<<<gAttn, 256, ATTN_SMEM_BYTES>>>();

    gemm_bf16_kernel<<<gGemm, 256, GEMM_SMEM_BYTES>>>(ab, w_o, out, ROWS, EMB, EMB);
}

// round 7
// speedup vs baseline: 2.1747x; 1.0344x over previous
#include <cuda_runtime.h>
#include <math.h>
#include <stdint.h>

// Problem constants
constexpr int S_LEN = 4096;
constexpr int BATCH = 2;
constexpr int EMB   = 512;   // E and also H*D
constexpr int NH    = 8;
constexpr int DH    = 64;
constexpr int HALF  = 256;   // sliding window half-width
constexpr int ROWS  = BATCH * S_LEN;  // 8192

// Scratch (allocation-free rule: __device__ globals)
__device__ float g_q[(size_t)ROWS * EMB];
__device__ float g_k[(size_t)ROWS * EMB];
__device__ float g_v[(size_t)ROWS * EMB];
__device__ float g_att[(size_t)ROWS * EMB];

// ---------------------------------------------------------------------------
// bf16 split helpers
// ---------------------------------------------------------------------------
__device__ __forceinline__ void split2(float x0, float x1,
                                       uint32_t& hp, uint32_t& lp) {
    asm("cvt.rn.bf16x2.f32 %0, %1, %2;" : "=r"(hp) : "f"(x1), "f"(x0));
    float h0 = __uint_as_float(hp << 16);
    float h1 = __uint_as_float(hp & 0xffff0000u);
    float r0 = x0 - h0;
    float r1 = x1 - h1;
    asm("cvt.rn.bf16x2.f32 %0, %1, %2;" : "=r"(lp) : "f"(r1), "f"(r0));
}

__device__ __forceinline__ void mma_bf16(float d[4], const uint32_t a[4],
                                         const uint32_t b[2]) {
    asm volatile(
        "mma.sync.aligned.m16n8k16.row.col.f32.bf16.bf16.f32 "
        "{%0,%1,%2,%3}, {%4,%5,%6,%7}, {%8,%9}, {%0,%1,%2,%3};\n"
        : "+f"(d[0]), "+f"(d[1]), "+f"(d[2]), "+f"(d[3])
        : "r"(a[0]), "r"(a[1]), "r"(a[2]), "r"(a[3]), "r"(b[0]), "r"(b[1]));
}

// ---------------------------------------------------------------------------
// Split-bf16 tensor-core GEMM (validated in R4). C[M,N] = A[M,K] @ B[K,N].
// ---------------------------------------------------------------------------
constexpr int GBM = 128, GBN = 128, GBK = 32;
constexpr int KP  = GBK / 2;
constexpr int ASTR = 20;
constexpr int BSTR = 136;
constexpr int A_STAGE = GBM * ASTR;
constexpr int B_STAGE = KP * BSTR;
constexpr int GEMM_SMEM_BYTES = (4 * A_STAGE + 4 * B_STAGE) * 4;

__global__ __launch_bounds__(256, 1) void gemm_bf16_kernel(
    const float* __restrict__ A, const float* __restrict__ B,
    float* __restrict__ C, int M, int N, int K)
{
    extern __shared__ uint32_t sm[];
    uint32_t* sAh = sm;
    uint32_t* sAl = sAh + 2 * A_STAGE;
    uint32_t* sBh = sAl + 2 * A_STAGE;
    uint32_t* sBl = sBh + 2 * B_STAGE;

    const int tid  = threadIdx.x;
    const int lane = tid & 31;
    const int wid  = tid >> 5;
    const int m_base = (wid >> 2) * 64;
    const int n_base = (wid & 3) * 32;
    const int row0 = blockIdx.y * GBM;
    const int col0 = blockIdx.x * GBN;

    const int arow  = tid >> 2;
    const int acolg = (tid & 3) * 8;
    const int akp   = (tid & 3) * 4;
    const int brow = tid >> 5;
    const int bcol = (tid & 31) * 4;

    const float* pA0 = A + (size_t)(row0 + arow) * K + acolg;
    const float* pA1 = A + (size_t)(row0 + arow + 64) * K + acolg;
    const float* pB00 = B + (size_t)(2 * brow) * N + col0 + bcol;
    const float* pB01 = B + (size_t)(2 * brow + 1) * N + col0 + bcol;
    const float* pB10 = B + (size_t)(2 * (brow + 8)) * N + col0 + bcol;
    const float* pB11 = B + (size_t)(2 * (brow + 8) + 1) * N + col0 + bcol;

    const int NT = K / GBK;

    float acc[4][4][4] = {};
    float4 fa00, fa01, fa10, fa11;
    float4 fb00, fb01, fb10, fb11;

    #define STORE_A(dsth, dstl, r, v0, v1)                                    \
        {                                                                     \
            uint32_t h0, l0, h1, l1, h2, l2, h3, l3;                          \
            split2((v0).x, (v0).y, h0, l0);                                   \
            split2((v0).z, (v0).w, h1, l1);                                   \
            split2((v1).x, (v1).y, h2, l2);                                   \
            split2((v1).z, (v1).w, h3, l3);                                   \
            *(uint4*)&(dsth)[(r) * ASTR + akp] = make_uint4(h0, h1, h2, h3);  \
            *(uint4*)&(dstl)[(r) * ASTR + akp] = make_uint4(l0, l1, l2, l3);  \
        }

    #define STORE_B(dsth, dstl, kp, v0, v1)                                   \
        {                                                                     \
            uint32_t h0, l0, h1, l1, h2, l2, h3, l3;                          \
            split2((v0).x, (v1).x, h0, l0);                                   \
            split2((v0).y, (v1).y, h1, l1);                                   \
            split2((v0).z, (v1).z, h2, l2);                                   \
            split2((v0).w, (v1).w, h3, l3);                                   \
            *(uint4*)&(dsth)[(kp) * BSTR + bcol] = make_uint4(h0, h1, h2, h3);\
            *(uint4*)&(dstl)[(kp) * BSTR + bcol] = make_uint4(l0, l1, l2, l3);\
        }

    fa00 = *(const float4*)(pA0);
    fa01 = *(const float4*)(pA0 + 4);
    fa10 = *(const float4*)(pA1);
    fa11 = *(const float4*)(pA1 + 4);
    fb00 = *(const float4*)(pB00);
    fb01 = *(const float4*)(pB01);
    fb10 = *(const float4*)(pB10);
    fb11 = *(const float4*)(pB11);

    STORE_A(sAh, sAl, arow, fa00, fa01);
    STORE_A(sAh, sAl, arow + 64, fa10, fa11);
    STORE_B(sBh, sBl, brow, fb00, fb01);
    STORE_B(sBh, sBl, brow + 8, fb10, fb11);
    __syncthreads();

    const int gr = lane >> 2;
    const int qc = lane & 3;

    for (int kt = 0; kt < NT; kt++) {
        if (kt + 1 < NT) {
            int ko = (kt + 1) * GBK;
            fa00 = *(const float4*)(pA0 + ko);
            fa01 = *(const float4*)(pA0 + ko + 4);
            fa10 = *(const float4*)(pA1 + ko);
            fa11 = *(const float4*)(pA1 + ko + 4);
            fb00 = *(const float4*)(pB00 + (size_t)ko * N);
            fb01 = *(const float4*)(pB01 + (size_t)ko * N);
            fb10 = *(const float4*)(pB10 + (size_t)ko * N);
            fb11 = *(const float4*)(pB11 + (size_t)ko * N);
        }

        const uint32_t* Ah = sAh + (kt & 1) * A_STAGE;
        const uint32_t* Al = sAl + (kt & 1) * A_STAGE;
        const uint32_t* Bh = sBh + (kt & 1) * B_STAGE;
        const uint32_t* Bl = sBl + (kt & 1) * B_STAGE;

        #pragma unroll
        for (int ks = 0; ks < 2; ks++) {
            const int kp0 = ks * 8 + qc;
            uint32_t ah[4][4], al[4][4], bh[4][2], bl[4][2];
            #pragma unroll
            for (int mt = 0; mt < 4; mt++) {
                const int m = m_base + mt * 16 + gr;
                ah[mt][0] = Ah[m * ASTR + kp0];
                ah[mt][1] = Ah[(m + 8) * ASTR + kp0];
                ah[mt][2] = Ah[m * ASTR + kp0 + 4];
                ah[mt][3] = Ah[(m + 8) * ASTR + kp0 + 4];
                al[mt][0] = Al[m * ASTR + kp0];
                al[mt][1] = Al[(m + 8) * ASTR + kp0];
                al[mt][2] = Al[m * ASTR + kp0 + 4];
                al[mt][3] = Al[(m + 8) * ASTR + kp0 + 4];
            }
            #pragma unroll
            for (int nt = 0; nt < 4; nt++) {
                const int n = n_base + nt * 8 + gr;
                bh[nt][0] = Bh[kp0 * BSTR + n];
                bh[nt][1] = Bh[(kp0 + 4) * BSTR + n];
                bl[nt][0] = Bl[kp0 * BSTR + n];
                bl[nt][1] = Bl[(kp0 + 4) * BSTR + n];
            }
            #pragma unroll
            for (int mt = 0; mt < 4; mt++)
                #pragma unroll
                for (int nt = 0; nt < 4; nt++) {
                    mma_bf16(acc[mt][nt], ah[mt], bh[nt]);
                    mma_bf16(acc[mt][nt], ah[mt], bl[nt]);
                    mma_bf16(acc[mt][nt], al[mt], bh[nt]);
                }
        }

        if (kt + 1 < NT) {
            uint32_t* dAh = sAh + ((kt + 1) & 1) * A_STAGE;
            uint32_t* dAl = sAl + ((kt + 1) & 1) * A_STAGE;
            uint32_t* dBh = sBh + ((kt + 1) & 1) * B_STAGE;
            uint32_t* dBl = sBl + ((kt + 1) & 1) * B_STAGE;
            STORE_A(dAh, dAl, arow, fa00, fa01);
            STORE_A(dAh, dAl, arow + 64, fa10, fa11);
            STORE_B(dBh, dBl, brow, fb00, fb01);
            STORE_B(dBh, dBl, brow + 8, fb10, fb11);
        }
        __syncthreads();
    }
    #undef STORE_A
    #undef STORE_B

    #pragma unroll
    for (int mt = 0; mt < 4; mt++) {
        #pragma unroll
        for (int nt = 0; nt < 4; nt++) {
            int r = row0 + m_base + mt * 16 + gr;
            int c = col0 + n_base + nt * 8 + 2 * qc;
            *(float2*)&C[(size_t)r * N + c] =
                make_float2(acc[mt][nt][0], acc[mt][nt][1]);
            *(float2*)&C[(size_t)(r + 8) * N + c] =
                make_float2(acc[mt][nt][2], acc[mt][nt][3]);
        }
    }
}

// ---------------------------------------------------------------------------
// Tensor-core windowed flash attention, bf16 hi/lo split, 512 threads/CTA.
// CTA = (b, h, 64-query tile); keys in 3 chunks of 192 (window span = 576).
// 16 warps: QK 4(m) x 4(n) -> warp tile 16 x 48; PV 4(m) x 4(n) -> 16 x 16.
// ---------------------------------------------------------------------------
constexpr int AQT = 64;
constexpr int AKT = 192;
constexpr int QSTR = 72;
constexpr int KSTR = 200;
constexpr int VSTR = 72;
constexpr int PSTR = 72;
constexpr int ATHREADS = 512;

constexpr int OFF_QH = 0;
constexpr int OFF_QL = OFF_QH + 32 * QSTR;
constexpr int OFF_KH = OFF_QL + 32 * QSTR;
constexpr int OFF_KL = OFF_KH + 32 * KSTR;
constexpr int OFF_VH = OFF_KL + 32 * KSTR;
constexpr int OFF_VL = OFF_VH + 96 * VSTR;
constexpr int OFF_PH = OFF_VL + 96 * VSTR;
constexpr int OFF_PL = OFF_PH + 96 * PSTR;
constexpr int OFF_RED = OFF_PL + 96 * PSTR;    // float[64*4]
constexpr int OFF_M  = OFF_RED + 256;
constexpr int OFF_L  = OFF_M + 64;
constexpr int OFF_F  = OFF_L + 64;
constexpr int ATTN_SMEM_WORDS = OFF_F + 64;
constexpr int ATTN_SMEM_BYTES = ATTN_SMEM_WORDS * 4;  // 182016

__global__ __launch_bounds__(ATHREADS, 1) void attn_tc_kernel()
{
    extern __shared__ uint32_t sm[];
    uint32_t* sQh = sm + OFF_QH;
    uint32_t* sQl = sm + OFF_QL;
    uint32_t* sKh = sm + OFF_KH;
    uint32_t* sKl = sm + OFF_KL;
    uint32_t* sVh = sm + OFF_VH;
    uint32_t* sVl = sm + OFF_VL;
    uint32_t* sPh = sm + OFF_PH;
    uint32_t* sPl = sm + OFF_PL;
    float* red = (float*)(sm + OFF_RED);
    float* mS  = (float*)(sm + OFF_M);
    float* lS  = (float*)(sm + OFF_L);
    float* fS  = (float*)(sm + OFF_F);

    const int tid  = threadIdx.x;
    const int lane = tid & 31;
    const int wid  = tid >> 5;     // 0..15
    const int gr = lane >> 2;
    const int qc = lane & 3;
    const int wm = wid >> 2;       // 0..3
    const int wn = wid & 3;        // 0..3
    const int m0 = wm * 16;

    const int t0 = blockIdx.x * AQT;
    const int h  = blockIdx.y;
    const int b  = blockIdx.z;
    const float slope = exp2f(-(float)(h + 1));

    const float* Qb = g_q   + (size_t)b * S_LEN * EMB + h * DH;
    const float* Kb = g_k   + (size_t)b * S_LEN * EMB + h * DH;
    const float* Vb = g_v   + (size_t)b * S_LEN * EMB + h * DH;
    float*       Ob = g_att + (size_t)b * S_LEN * EMB + h * DH;

    // Load Q tile (split bf16, kp-major)
    for (int idx = tid; idx < AQT * 16; idx += ATHREADS) {
        int q = idx >> 4;
        int dg = idx & 15;
        float4 v = *(const float4*)&Qb[(size_t)(t0 + q) * EMB + dg * 4];
        uint32_t h0, l0, h1, l1;
        split2(v.x, v.y, h0, l0);
        split2(v.z, v.w, h1, l1);
        int kp = dg * 2;
        sQh[kp * QSTR + q] = h0;        sQl[kp * QSTR + q] = l0;
        sQh[(kp + 1) * QSTR + q] = h1;  sQl[(kp + 1) * QSTR + q] = l1;
    }
    if (tid < AQT) { mS[tid] = -1e30f; lS[tid] = 0.0f; }

    float o[2][4] = {};

    const int base = t0 - HALF;

    #pragma unroll 1
    for (int c = 0; c < 3; c++) {
        const int cs = base + c * AKT;
        if (cs + AKT <= 0 || cs >= S_LEN) continue;

        // ---- load K chunk ----
        for (int idx = tid; idx < AKT * 16; idx += ATHREADS) {
            int key = idx >> 4;
            int dg = idx & 15;
            int T = cs + key;
            float4 kv = make_float4(0.f, 0.f, 0.f, 0.f);
            if (T >= 0 && T < S_LEN)
                kv = *(const float4*)&Kb[(size_t)T * EMB + dg * 4];
            uint32_t h0, l0, h1, l1;
            split2(kv.x, kv.y, h0, l0);
            split2(kv.z, kv.w, h1, l1);
            int kp = dg * 2;
            sKh[kp * KSTR + key] = h0;        sKl[kp * KSTR + key] = l0;
            sKh[(kp + 1) * KSTR + key] = h1;  sKl[(kp + 1) * KSTR + key] = l1;
        }
        // ---- load V chunk transposed ----
        for (int idx = tid; idx < 96 * 16; idx += ATHREADS) {
            int kp = idx >> 4;
            int dg = idx & 15;
            int d = dg * 4;
            int T0 = cs + 2 * kp, T1 = T0 + 1;
            float4 v0 = make_float4(0.f, 0.f, 0.f, 0.f);
            float4 v1 = make_float4(0.f, 0.f, 0.f, 0.f);
            if (T0 >= 0 && T0 < S_LEN) v0 = *(const float4*)&Vb[(size_t)T0 * EMB + d];
            if (T1 >= 0 && T1 < S_LEN) v1 = *(const float4*)&Vb[(size_t)T1 * EMB + d];
            uint32_t hp, lp;
            split2(v0.x, v1.x, hp, lp); sVh[kp * VSTR + d + 0] = hp; sVl[kp * VSTR + d + 0] = lp;
            split2(v0.y, v1.y, hp, lp); sVh[kp * VSTR + d + 1] = hp; sVl[kp * VSTR + d + 1] = lp;
            split2(v0.z, v1.z, hp, lp); sVh[kp * VSTR + d + 2] = hp; sVl[kp * VSTR + d + 2] = lp;
            split2(v0.w, v1.w, hp, lp); sVh[kp * VSTR + d + 3] = hp; sVl[kp * VSTR + d + 3] = lp;
        }
        __syncthreads();

        // ---- S = Q @ K^T : warp tile 16 x 48, 6 n-tiles, 4 k-steps ----
        float s[6][4];
        #pragma unroll
        for (int nt = 0; nt < 6; nt++)
            #pragma unroll
            for (int i = 0; i < 4; i++) s[nt][i] = 0.f;

        const int nbase = wn * 48;
        #pragma unroll
        for (int ks = 0; ks < 4; ks++) {
            const int kpa = ks * 8 + qc;
            uint32_t ah[4], al[4];
            ah[0] = sQh[kpa * QSTR + m0 + gr];
            ah[1] = sQh[kpa * QSTR + m0 + gr + 8];
            ah[2] = sQh[(kpa + 4) * QSTR + m0 + gr];
            ah[3] = sQh[(kpa + 4) * QSTR + m0 + gr + 8];
            al[0] = sQl[kpa * QSTR + m0 + gr];
            al[1] = sQl[kpa * QSTR + m0 + gr + 8];
            al[2] = sQl[(kpa + 4) * QSTR + m0 + gr];
            al[3] = sQl[(kpa + 4) * QSTR + m0 + gr + 8];
            #pragma unroll
            for (int nt = 0; nt < 6; nt++) {
                int n = nbase + nt * 8 + gr;
                uint32_t bh[2], bl[2];
                bh[0] = sKh[kpa * KSTR + n];
                bh[1] = sKh[(kpa + 4) * KSTR + n];
                bl[0] = sKl[kpa * KSTR + n];
                bl[1] = sKl[(kpa + 4) * KSTR + n];
                mma_bf16(s[nt], ah, bh);
                mma_bf16(s[nt], ah, bl);
                mma_bf16(s[nt], al, bh);
            }
        }

        // ---- scale + ALiBi + window mask; per-row max ----
        const int trow0 = t0 + m0 + gr;
        const int trow1 = trow0 + 8;
        float mx0 = -1e30f, mx1 = -1e30f;
        #pragma unroll
        for (int nt = 0; nt < 6; nt++) {
            int T0 = cs + nbase + nt * 8 + 2 * qc;
            int T1 = T0 + 1;
            bool in0 = (T0 >= 0) && (T0 < S_LEN);
            bool in1 = (T1 >= 0) && (T1 < S_LEN);
            int a00 = abs(trow0 - T0), a01 = abs(trow0 - T1);
            int a10 = abs(trow1 - T0), a11 = abs(trow1 - T1);
            s[nt][0] = (in0 && a00 <= HALF) ? fmaf(s[nt][0], 0.125f, -slope * (float)a00) : -1e30f;
            s[nt][1] = (in1 && a01 <= HALF) ? fmaf(s[nt][1], 0.125f, -slope * (float)a01) : -1e30f;
            s[nt][2] = (in0 && a10 <= HALF) ? fmaf(s[nt][2], 0.125f, -slope * (float)a10) : -1e30f;
            s[nt][3] = (in1 && a11 <= HALF) ? fmaf(s[nt][3], 0.125f, -slope * (float)a11) : -1e30f;
            mx0 = fmaxf(mx0, fmaxf(s[nt][0], s[nt][1]));
            mx1 = fmaxf(mx1, fmaxf(s[nt][2], s[nt][3]));
        }
        mx0 = fmaxf(mx0, __shfl_xor_sync(0xffffffffu, mx0, 1));
        mx0 = fmaxf(mx0, __shfl_xor_sync(0xffffffffu, mx0, 2));
        mx1 = fmaxf(mx1, __shfl_xor_sync(0xffffffffu, mx1, 1));
        mx1 = fmaxf(mx1, __shfl_xor_sync(0xffffffffu, mx1, 2));
        if (qc == 0) {
            red[(m0 + gr) * 4 + wn] = mx0;
            red[(m0 + gr + 8) * 4 + wn] = mx1;
        }
        __syncthreads();

        if (tid < AQT) {
            float cm = fmaxf(fmaxf(red[tid * 4], red[tid * 4 + 1]),
                             fmaxf(red[tid * 4 + 2], red[tid * 4 + 3]));
            float mold = mS[tid];
            float mnew = fmaxf(mold, cm);
            fS[tid] = __expf(mold - mnew);
            mS[tid] = mnew;
        }
        __syncthreads();

        // ---- exp, stage P (split bf16), partial sums, rescale O ----
        const float mrow0 = mS[m0 + gr];
        const float mrow1 = mS[m0 + gr + 8];
        float sum0 = 0.f, sum1 = 0.f;
        #pragma unroll
        for (int nt = 0; nt < 6; nt++) {
            float p00 = (s[nt][0] > -5e29f) ? __expf(s[nt][0] - mrow0) : 0.f;
            float p01 = (s[nt][1] > -5e29f) ? __expf(s[nt][1] - mrow0) : 0.f;
            float p10 = (s[nt][2] > -5e29f) ? __expf(s[nt][2] - mrow1) : 0.f;
            float p11 = (s[nt][3] > -5e29f) ? __expf(s[nt][3] - mrow1) : 0.f;
            sum0 += p00 + p01;
            sum1 += p10 + p11;
            int kp = wn * 24 + nt * 4 + qc;
            uint32_t hp, lp;
            split2(p00, p01, hp, lp);
            sPh[kp * PSTR + m0 + gr] = hp;
            sPl[kp * PSTR + m0 + gr] = lp;
            split2(p10, p11, hp, lp);
            sPh[kp * PSTR + m0 + gr + 8] = hp;
            sPl[kp * PSTR + m0 + gr + 8] = lp;
        }
        sum0 += __shfl_xor_sync(0xffffffffu, sum0, 1);
        sum0 += __shfl_xor_sync(0xffffffffu, sum0, 2);
        sum1 += __shfl_xor_sync(0xffffffffu, sum1, 1);
        sum1 += __shfl_xor_sync(0xffffffffu, sum1, 2);
        if (qc == 0) {
            red[(m0 + gr) * 4 + wn] = sum0;
            red[(m0 + gr + 8) * 4 + wn] = sum1;
        }
        const float f0 = fS[m0 + gr];
        const float f1 = fS[m0 + gr + 8];
        #pragma unroll
        for (int nt = 0; nt < 2; nt++) {
            o[nt][0] *= f0; o[nt][1] *= f0;
            o[nt][2] *= f1; o[nt][3] *= f1;
        }
        __syncthreads();

        if (tid < AQT)
            lS[tid] = lS[tid] * fS[tid] + red[tid * 4] + red[tid * 4 + 1]
                      + red[tid * 4 + 2] + red[tid * 4 + 3];

        // ---- O += P @ V : warp tile 16 x 16, 2 n-tiles, 12 k-steps ----
        const int nb2 = wn * 16;
        #pragma unroll
        for (int ks = 0; ks < 12; ks++) {
            const int kpa = ks * 8 + qc;
            uint32_t ah[4], al[4];
            ah[0] = sPh[kpa * PSTR + m0 + gr];
            ah[1] = sPh[kpa * PSTR + m0 + gr + 8];
            ah[2] = sPh[(kpa + 4) * PSTR + m0 + gr];
            ah[3] = sPh[(kpa + 4) * PSTR + m0 + gr + 8];
            al[0] = sPl[kpa * PSTR + m0 + gr];
            al[1] = sPl[kpa * PSTR + m0 + gr + 8];
            al[2] = sPl[(kpa + 4) * PSTR + m0 + gr];
            al[3] = sPl[(kpa + 4) * PSTR + m0 + gr + 8];
            #pragma unroll
            for (int nt = 0; nt < 2; nt++) {
                int n = nb2 + nt * 8 + gr;
                uint32_t bh[2], bl[2];
                bh[0] = sVh[kpa * VSTR + n];
                bh[1] = sVh[(kpa + 4) * VSTR + n];
                bl[0] = sVl[kpa * VSTR + n];
                bl[1] = sVl[(kpa + 4) * VSTR + n];
                mma_bf16(o[nt], ah, bh);
                mma_bf16(o[nt], ah, bl);
                mma_bf16(o[nt], al, bh);
            }
        }
        __syncthreads();
    }

    // ---- normalize and write ----
    const int trow0 = t0 + m0 + gr;
    const float inv0 = 1.0f / lS[m0 + gr];
    const float inv1 = 1.0f / lS[m0 + gr + 8];
    #pragma unroll
    for (int nt = 0; nt < 2; nt++) {
        int d = wn * 16 + nt * 8 + 2 * qc;
        *(float2*)&Ob[(size_t)trow0 * EMB + d] =
            make_float2(o[nt][0] * inv0, o[nt][1] * inv0);
        *(float2*)&Ob[(size_t)(trow0 + 8) * EMB + d] =
            make_float2(o[nt][2] * inv1, o[nt][3] * inv1);
    }
}

// ---------------------------------------------------------------------------
extern "C" void kernel_launch(void* const* d_in, const int* in_sizes, int n_in,
                              void* d_out, int out_size)
{
    (void)in_sizes; (void)n_in; (void)out_size;
    const float* inputs_q  = (const float*)d_in[0];
    const float* inputs_kv = (const float*)d_in[1];
    const float* w_q = (const float*)d_in[2];
    const float* w_k = (const float*)d_in[3];
    const float* w_v = (const float*)d_in[4];
    const float* w_o = (const float*)d_in[5];
    float* out = (float*)d_out;

    float *qb, *kb, *vb, *ab;
    cudaGetSymbolAddress((void**)&qb, g_q);
    cudaGetSymbolAddress((void**)&kb, g_k);
    cudaGetSymbolAddress((void**)&vb, g_v);
    cudaGetSymbolAddress((void**)&ab, g_att);

    cudaFuncSetAttribute(gemm_bf16_kernel,
                         cudaFuncAttributeMaxDynamicSharedMemorySize,
                         GEMM_SMEM_BYTES);
    cudaFuncSetAttribute(attn_tc_kernel,
                         cudaFuncAttributeMaxDynamicSharedMemorySize,
                         ATTN_SMEM_BYTES);

    dim3 gGemm(EMB / GBN, ROWS / GBM);   // (4, 64)
    gemm_bf16_kernel<<<gGemm, 256, GEMM_SMEM_BYTES>>>(inputs_q,  w_q, qb, ROWS, EMB, EMB);
    gemm_bf16_kernel<<<gGemm, 256, GEMM_SMEM_BYTES>>>(inputs_kv, w_k, kb, ROWS, EMB, EMB);
    gemm_bf16_kernel<<<gGemm, 256, GEMM_SMEM_BYTES>>>(inputs_kv, w_v, vb, ROWS, EMB, EMB);

    dim3 gAttn(S_LEN / AQT, NH, BATCH);  // (64, 8, 2)
    attn_tc_kernel<<<gAttn, ATHREADS, ATTN_SMEM_BYTES>>>();

    gemm_bf16_kernel<<<gGemm, 256, GEMM_SMEM_BYTES>>>(ab, w_o, out, ROWS, EMB, EMB);
}